// round 6
// baseline (speedup 1.0000x reference)
#include <cuda_runtime.h>
#include <cuda_bf16.h>
#include <cstdint>

#define BB 64
#define TT 512
#define EE 256
#define HH 256          // per-direction hidden
#define GG 1024         // 4*H
#define KK 12
#define START_TAG 10
#define STOP_TAG 11
#define NEGV -10000.0f

// ---------------- device scratch (allowed: __device__ globals) ----------------
__device__ float g_xproj[(size_t)2 * TT * BB * GG];   // [dir][t][b][1024]  268 MB
__device__ float g_h[(size_t)2 * TT * BB * HH];       // [dir][t][b][256]   67 MB
__device__ float g_c[(size_t)2 * BB * HH];            // [dir][b][256]
__device__ float g_feats[(size_t)TT * BB * KK];       // [t][b][12]

// =============================================================================
// Kernel 1: embedding gather + input projection GEMM
//   C[m][n] = emb[tok[m]][:] . W[n][:]  + bias(n),  m in [0,32768), n in [0,2048)
//   n < 1024 -> forward (Wf_ih), else backward (Wb_ih)
//   output written as g_xproj[dir][t][b][g]
// =============================================================================
__global__ void k_xproj(const int* __restrict__ sent,
                        const float* __restrict__ emb,
                        const float* __restrict__ Wf,
                        const float* __restrict__ Wb,
                        const float* __restrict__ bf_ih, const float* __restrict__ bf_hh,
                        const float* __restrict__ bb_ih, const float* __restrict__ bb_hh)
{
    const int BM = 64, BN = 64, BK = 16;
    __shared__ float As[BK][BM + 4];   // transposed: As[k][m]
    __shared__ float Bs[BK][BN + 4];   // transposed: Bs[k][n]
    __shared__ int   toks[BM];

    const int m0 = blockIdx.x * BM;
    const int n0 = blockIdx.y * BN;
    const int tid = threadIdx.x;
    const int tx = tid & 15;       // 0..15  (n direction)
    const int ty = tid >> 4;       // 0..15  (m direction)

    if (tid < BM) toks[tid] = sent[m0 + tid];
    __syncthreads();

    const int dir = (n0 < GG) ? 0 : 1;
    const int nw0 = (dir == 0) ? n0 : (n0 - GG);
    const float* __restrict__ Wsrc = (dir == 0) ? Wf : Wb;

    float acc[4][4];
#pragma unroll
    for (int i = 0; i < 4; i++)
#pragma unroll
        for (int j = 0; j < 4; j++) acc[i][j] = 0.f;

    const int lr  = tid >> 2;        // 0..63 row for loads
    const int lc4 = (tid & 3) * 4;   // 0,4,8,12 k-offset for loads

    for (int k0 = 0; k0 < EE; k0 += BK) {
        // load A tile (gathered embedding rows), transposed store
        {
            const float4 v = *(const float4*)(emb + (size_t)toks[lr] * EE + k0 + lc4);
            As[lc4 + 0][lr] = v.x; As[lc4 + 1][lr] = v.y;
            As[lc4 + 2][lr] = v.z; As[lc4 + 3][lr] = v.w;
        }
        // load B tile (weight rows), transposed store
        {
            const float4 v = *(const float4*)(Wsrc + (size_t)(nw0 + lr) * EE + k0 + lc4);
            Bs[lc4 + 0][lr] = v.x; Bs[lc4 + 1][lr] = v.y;
            Bs[lc4 + 2][lr] = v.z; Bs[lc4 + 3][lr] = v.w;
        }
        __syncthreads();
#pragma unroll
        for (int k = 0; k < BK; k++) {
            const float4 a = *(const float4*)&As[k][ty * 4];
            const float4 b = *(const float4*)&Bs[k][tx * 4];
            acc[0][0] += a.x * b.x; acc[0][1] += a.x * b.y; acc[0][2] += a.x * b.z; acc[0][3] += a.x * b.w;
            acc[1][0] += a.y * b.x; acc[1][1] += a.y * b.y; acc[1][2] += a.y * b.z; acc[1][3] += a.y * b.w;
            acc[2][0] += a.z * b.x; acc[2][1] += a.z * b.y; acc[2][2] += a.z * b.z; acc[2][3] += a.z * b.w;
            acc[3][0] += a.w * b.x; acc[3][1] += a.w * b.y; acc[3][2] += a.w * b.z; acc[3][3] += a.w * b.w;
        }
        __syncthreads();
    }

    // biases for this thread's 4 output columns
    const int gbase = nw0 + tx * 4;
    float bsum[4];
#pragma unroll
    for (int j = 0; j < 4; j++) {
        const int g = gbase + j;
        bsum[j] = (dir == 0) ? (bf_ih[g] + bf_hh[g]) : (bb_ih[g] + bb_hh[g]);
    }

#pragma unroll
    for (int i = 0; i < 4; i++) {
        const int m = m0 + ty * 4 + i;
        const int t = m & (TT - 1);
        const int b = m >> 9;                       // m / 512
        float4 o;
        o.x = acc[i][0] + bsum[0];
        o.y = acc[i][1] + bsum[1];
        o.z = acc[i][2] + bsum[2];
        o.w = acc[i][3] + bsum[3];
        *(float4*)&g_xproj[(((size_t)dir * TT + t) * BB + b) * GG + gbase] = o;
    }
}

// =============================================================================
// Kernel 2: one LSTM timestep, both directions.
//   grid = 128 blocks: dir = bid>>6, slice = bid&63 (4 hidden channels each)
//   block computes the 16 gate rows {gate*256 + slice*4 + kl} for all 64 batches,
//   then updates c/h for its 4 channels.
// =============================================================================
#define HSTR 260   // padded h row stride (floats)
#define STEP_SMEM_FLOATS (BB * HSTR + 16 * HH + 16 * 65)

__global__ void k_step(const float* __restrict__ Whf,
                       const float* __restrict__ Whb,
                       int s)
{
    extern __shared__ float sm[];
    float* h_s = sm;                          // [64][260]
    float* W_s = sm + BB * HSTR;              // [16][256]
    float* g_s = W_s + 16 * HH;               // [16][65]

    const int bid = blockIdx.x;
    const int dir = bid >> 6;
    const int slice = bid & 63;
    const int k0 = slice * 4;
    const int tid = threadIdx.x;

    const int t = (dir == 0) ? s : (TT - 1 - s);
    const float* __restrict__ Wsrc = (dir == 0) ? Whf : Whb;

    if (s > 0) {
        const int tprev = (dir == 0) ? (t - 1) : (t + 1);
        const float* __restrict__ hprev = g_h + ((size_t)dir * TT + tprev) * BB * HH;
        // load h[64][256]
        for (int f = tid; f < (BB * HH / 4); f += 256) {
            const int b = f >> 6;
            const int c = (f & 63) * 4;
            const float4 v = *(const float4*)(hprev + b * HH + c);
            *(float4*)&h_s[b * HSTR + c] = v;
        }
        // load 16 weight rows
        for (int f = tid; f < (16 * HH / 4); f += 256) {
            const int r = f >> 6;                   // local row = gate*4+kl
            const int c = (f & 63) * 4;
            const int gate = r >> 2, kl = r & 3;
            const float4 v = *(const float4*)(Wsrc + (size_t)(gate * HH + k0 + kl) * HH + c);
            *(float4*)&W_s[r * HH + c] = v;
        }
    }
    __syncthreads();

    // --- dot phase: thread = (row-pair, batch-pair) ---
    {
        const int rp = tid >> 5;         // 0..7
        const int bp = tid & 31;         // 0..31
        const int r0 = rp * 2, r1 = r0 + 1;
        const int b0 = bp * 2, b1 = b0 + 1;
        float a00 = 0.f, a01 = 0.f, a10 = 0.f, a11 = 0.f;
        if (s > 0) {
            const float4* __restrict__ w0 = (const float4*)(W_s + r0 * HH);
            const float4* __restrict__ w1 = (const float4*)(W_s + r1 * HH);
            const float4* __restrict__ hA = (const float4*)(h_s + b0 * HSTR);
            const float4* __restrict__ hB = (const float4*)(h_s + b1 * HSTR);
#pragma unroll 8
            for (int j = 0; j < HH / 4; j++) {
                const float4 wv0 = w0[j], wv1 = w1[j];
                const float4 ha = hA[j], hb = hB[j];
                a00 += wv0.x * ha.x + wv0.y * ha.y + wv0.z * ha.z + wv0.w * ha.w;
                a01 += wv0.x * hb.x + wv0.y * hb.y + wv0.z * hb.z + wv0.w * hb.w;
                a10 += wv1.x * ha.x + wv1.y * ha.y + wv1.z * ha.z + wv1.w * ha.w;
                a11 += wv1.x * hb.x + wv1.y * hb.y + wv1.z * hb.z + wv1.w * hb.w;
            }
        }
        g_s[r0 * 65 + b0] = a00;
        g_s[r0 * 65 + b1] = a01;
        g_s[r1 * 65 + b0] = a10;
        g_s[r1 * 65 + b1] = a11;
    }
    __syncthreads();

    // --- update phase: thread = (b, kl) ---
    {
        const int b  = tid >> 2;
        const int kl = tid & 3;
        const int kg = k0 + kl;
        const size_t xbase = (((size_t)dir * TT + t) * BB + b) * GG + kg;
        const float gi = g_s[(0 + kl) * 65 + b]  + g_xproj[xbase];
        const float gf = g_s[(4 + kl) * 65 + b]  + g_xproj[xbase + 256];
        const float gg = g_s[(8 + kl) * 65 + b]  + g_xproj[xbase + 512];
        const float go = g_s[(12 + kl) * 65 + b] + g_xproj[xbase + 768];

        const float ii = 1.f / (1.f + __expf(-gi));
        const float ff = 1.f / (1.f + __expf(-gf));
        const float gt = tanhf(gg);
        const float oo = 1.f / (1.f + __expf(-go));

        const size_t cidx = ((size_t)dir * BB + b) * HH + kg;
        const float cp = (s == 0) ? 0.f : g_c[cidx];
        const float c = ff * cp + ii * gt;
        g_c[cidx] = c;
        const float h = oo * tanhf(c);
        g_h[(((size_t)dir * TT + t) * BB + b) * HH + kg] = h;
    }
}

// =============================================================================
// Kernel 3: feats[t][b][k] = hcat[t][b][:512] . W_out[k][:512] + b_out[k]
//   grid = 512 (per t), block 256: thread = (b, kq), kq covers 3 tags
// =============================================================================
__global__ void k_feats(const float* __restrict__ Wout, const float* __restrict__ bout)
{
    __shared__ float Ws[KK * 512];
    __shared__ float bs[KK];
    const int t = blockIdx.x;
    const int tid = threadIdx.x;
    for (int i = tid; i < KK * 512; i += 256) Ws[i] = Wout[i];
    if (tid < KK) bs[tid] = bout[tid];
    __syncthreads();

    const int b = tid >> 2;
    const int kq = tid & 3;
    const float* __restrict__ hf = g_h + (((size_t)0 * TT + t) * BB + b) * HH;
    const float* __restrict__ hb = g_h + (((size_t)1 * TT + t) * BB + b) * HH;

    float acc[3] = {0.f, 0.f, 0.f};
    for (int j = 0; j < HH; j += 4) {
        const float4 hv = *(const float4*)(hf + j);
#pragma unroll
        for (int q = 0; q < 3; q++) {
            const int k = kq * 3 + q;
            const float4 wv = *(const float4*)(Ws + k * 512 + j);
            acc[q] += hv.x * wv.x + hv.y * wv.y + hv.z * wv.z + hv.w * wv.w;
        }
    }
    for (int j = 0; j < HH; j += 4) {
        const float4 hv = *(const float4*)(hb + j);
#pragma unroll
        for (int q = 0; q < 3; q++) {
            const int k = kq * 3 + q;
            const float4 wv = *(const float4*)(Ws + k * 512 + 256 + j);
            acc[q] += hv.x * wv.x + hv.y * wv.y + hv.z * wv.z + hv.w * wv.w;
        }
    }
#pragma unroll
    for (int q = 0; q < 3; q++) {
        const int k = kq * 3 + q;
        g_feats[((size_t)t * BB + b) * KK + k] = acc[q] + bs[k];
    }
}

// =============================================================================
// Kernel 4: CRF Viterbi decode + backtrack. One warp per batch element.
//   out[0..63]            = path_scores
//   out[64 + b*512 + t]   = path (as float)
// =============================================================================
__global__ void k_crf(const float* __restrict__ trans,
                      const int* __restrict__ slen,
                      float* __restrict__ out)
{
    __shared__ unsigned char bp_s[TT][KK];
    const int b = blockIdx.x;
    const int lane = threadIdx.x;

    float tr[KK];
#pragma unroll
    for (int kp = 0; kp < KK; kp++)
        tr[kp] = (lane < KK) ? trans[lane * KK + kp] : -1e30f;
    const float tstop = (lane < KK) ? trans[STOP_TAG * KK + lane] : -1e30f;

    float dp = (lane == START_TAG) ? 0.f : NEGV;
    if (lane >= KK) dp = -1e30f;
    const int len = slen[b];

    float fnext = (lane < KK) ? g_feats[((size_t)0 * BB + b) * KK + lane] : 0.f;

    for (int t = 0; t < TT; t++) {
        const float fcur = fnext;
        if (t < TT - 1)
            fnext = (lane < KK) ? g_feats[((size_t)(t + 1) * BB + b) * KK + lane] : 0.f;

        float best = -3.4e38f;
        int barg = 0;
#pragma unroll
        for (int kp = 0; kp < KK; kp++) {
            const float dpv = __shfl_sync(0xffffffffu, dp, kp);
            const float sc = dpv + tr[kp];
            if (sc > best) { best = sc; barg = kp; }   // strict > keeps first (lowest) index
        }
        const bool valid = (t < len);
        dp = valid ? (best + fcur) : dp;
        const int bpv = valid ? barg : lane;
        if (lane < KK) bp_s[t][lane] = (unsigned char)bpv;
    }

    const float tv = (lane < KK) ? (dp + tstop) : -3.4e38f;
    __syncwarp();

    float best = -3.4e38f;
    int barg = 0;
#pragma unroll
    for (int k = 0; k < KK; k++) {
        const float v = __shfl_sync(0xffffffffu, tv, k);
        if (v > best) { best = v; barg = k; }
    }

    if (lane == 0) {
        out[b] = best;
        int tag = barg;
        float* po = out + BB + (size_t)b * TT;
        for (int t = TT - 1; t >= 0; t--) {
            po[t] = (float)tag;
            tag = (int)bp_s[t][tag];
        }
    }
}

// =============================================================================
// host launcher
// =============================================================================
extern "C" void kernel_launch(void* const* d_in, const int* in_sizes, int n_in,
                              void* d_out, int out_size)
{
    (void)in_sizes; (void)n_in; (void)out_size;
    const int*   sentence = (const int*)  d_in[0];
    const int*   slen     = (const int*)  d_in[1];
    const float* emb      = (const float*)d_in[2];
    const float* Wf_ih    = (const float*)d_in[3];
    const float* Wf_hh    = (const float*)d_in[4];
    const float* bf_ih    = (const float*)d_in[5];
    const float* bf_hh    = (const float*)d_in[6];
    const float* Wb_ih    = (const float*)d_in[7];
    const float* Wb_hh    = (const float*)d_in[8];
    const float* bb_ih    = (const float*)d_in[9];
    const float* bb_hh    = (const float*)d_in[10];
    const float* W_out    = (const float*)d_in[11];
    const float* b_out    = (const float*)d_in[12];
    const float* trans    = (const float*)d_in[13];
    float* out = (float*)d_out;

    const size_t step_smem = (size_t)STEP_SMEM_FLOATS * sizeof(float);
    cudaFuncSetAttribute(k_step, cudaFuncAttributeMaxDynamicSharedMemorySize,
                         (int)step_smem);

    // 1) input projection for both directions
    k_xproj<<<dim3((BB * TT) / 64, (2 * GG) / 64), 256>>>(
        sentence, emb, Wf_ih, Wb_ih, bf_ih, bf_hh, bb_ih, bb_hh);

    // 2) 512 sequential LSTM steps (fwd ascending, bwd descending, fused)
    for (int s = 0; s < TT; s++) {
        k_step<<<128, 256, step_smem>>>(Wf_hh, Wb_hh, s);
    }

    // 3) emission features
    k_feats<<<TT, 256>>>(W_out, b_out);

    // 4) CRF Viterbi decode
    k_crf<<<BB, 32>>>(trans, slen, out);
}

// round 7
// speedup vs baseline: 1.4739x; 1.4739x over previous
#include <cuda_runtime.h>
#include <cuda_bf16.h>
#include <cstdint>

#define BB 64
#define TT 512
#define EE 256
#define HH 256          // per-direction hidden
#define GG 1024         // 4*H
#define KK 12
#define START_TAG 10
#define STOP_TAG 11
#define NEGV -10000.0f

// ---------------- device scratch (allowed: __device__ globals) ----------------
__device__ float g_xproj[(size_t)2 * TT * BB * GG];   // [dir][t][b][1024]  268 MB
__device__ float g_h[(size_t)2 * TT * BB * HH];       // [dir][t][b][256]   67 MB
__device__ float g_feats[(size_t)TT * BB * KK];       // [t][b][12]
__device__ unsigned g_arrive[TT];                     // per-step barrier counters

// =============================================================================
// Kernel 1: embedding gather + input projection GEMM
//   C[m][n] = emb[tok[m]][:] . W[n][:]  + bias(n),  m in [0,32768), n in [0,2048)
// =============================================================================
__global__ void k_xproj(const int* __restrict__ sent,
                        const float* __restrict__ emb,
                        const float* __restrict__ Wf,
                        const float* __restrict__ Wb,
                        const float* __restrict__ bf_ih, const float* __restrict__ bf_hh,
                        const float* __restrict__ bb_ih, const float* __restrict__ bb_hh)
{
    const int BM = 64, BN = 64, BK = 16;
    __shared__ float As[BK][BM + 4];   // transposed: As[k][m]
    __shared__ float Bs[BK][BN + 4];   // transposed: Bs[k][n]
    __shared__ int   toks[BM];

    const int m0 = blockIdx.x * BM;
    const int n0 = blockIdx.y * BN;
    const int tid = threadIdx.x;
    const int tx = tid & 15;       // 0..15  (n direction)
    const int ty = tid >> 4;       // 0..15  (m direction)

    if (tid < BM) toks[tid] = sent[m0 + tid];
    __syncthreads();

    const int dir = (n0 < GG) ? 0 : 1;
    const int nw0 = (dir == 0) ? n0 : (n0 - GG);
    const float* __restrict__ Wsrc = (dir == 0) ? Wf : Wb;

    float acc[4][4];
#pragma unroll
    for (int i = 0; i < 4; i++)
#pragma unroll
        for (int j = 0; j < 4; j++) acc[i][j] = 0.f;

    const int lr  = tid >> 2;        // 0..63 row for loads
    const int lc4 = (tid & 3) * 4;   // 0,4,8,12 k-offset for loads

    for (int k0 = 0; k0 < EE; k0 += BK) {
        {
            const float4 v = *(const float4*)(emb + (size_t)toks[lr] * EE + k0 + lc4);
            As[lc4 + 0][lr] = v.x; As[lc4 + 1][lr] = v.y;
            As[lc4 + 2][lr] = v.z; As[lc4 + 3][lr] = v.w;
        }
        {
            const float4 v = *(const float4*)(Wsrc + (size_t)(nw0 + lr) * EE + k0 + lc4);
            Bs[lc4 + 0][lr] = v.x; Bs[lc4 + 1][lr] = v.y;
            Bs[lc4 + 2][lr] = v.z; Bs[lc4 + 3][lr] = v.w;
        }
        __syncthreads();
#pragma unroll
        for (int k = 0; k < BK; k++) {
            const float4 a = *(const float4*)&As[k][ty * 4];
            const float4 b = *(const float4*)&Bs[k][tx * 4];
            acc[0][0] += a.x * b.x; acc[0][1] += a.x * b.y; acc[0][2] += a.x * b.z; acc[0][3] += a.x * b.w;
            acc[1][0] += a.y * b.x; acc[1][1] += a.y * b.y; acc[1][2] += a.y * b.z; acc[1][3] += a.y * b.w;
            acc[2][0] += a.z * b.x; acc[2][1] += a.z * b.y; acc[2][2] += a.z * b.z; acc[2][3] += a.z * b.w;
            acc[3][0] += a.w * b.x; acc[3][1] += a.w * b.y; acc[3][2] += a.w * b.z; acc[3][3] += a.w * b.w;
        }
        __syncthreads();
    }

    const int gbase = nw0 + tx * 4;
    float bsum[4];
#pragma unroll
    for (int j = 0; j < 4; j++) {
        const int g = gbase + j;
        bsum[j] = (dir == 0) ? (bf_ih[g] + bf_hh[g]) : (bb_ih[g] + bb_hh[g]);
    }

#pragma unroll
    for (int i = 0; i < 4; i++) {
        const int m = m0 + ty * 4 + i;
        const int t = m & (TT - 1);
        const int b = m >> 9;                       // m / 512
        float4 o;
        o.x = acc[i][0] + bsum[0];
        o.y = acc[i][1] + bsum[1];
        o.z = acc[i][2] + bsum[2];
        o.w = acc[i][3] + bsum[3];
        *(float4*)&g_xproj[(((size_t)dir * TT + t) * BB + b) * GG + gbase] = o;
    }
}

// =============================================================================
// Kernel 2: PERSISTENT bidirectional LSTM.
//   128 blocks (= 2 dirs x 64 channel-slices), all co-resident (<=148 SMs).
//   Each block: caches its 16 W_hh rows in smem ONCE, keeps cell state c in
//   registers, loops over all 512 timesteps with a software grid barrier
//   (per-step arrival counter) between steps.
// =============================================================================
#define HSTR 260   // padded h row stride (floats) — conflict-free LDS.128
#define LSTM_SMEM_FLOATS (BB * HSTR + 16 * HH + 16 * 65)
#define NBLK 128

__global__ void __launch_bounds__(256, 1) k_lstm(const float* __restrict__ Whf,
                                                 const float* __restrict__ Whb)
{
    extern __shared__ float sm[];
    float* h_s = sm;                          // [64][260]
    float* W_s = sm + BB * HSTR;              // [16][256]
    float* g_s = W_s + 16 * HH;               // [16][65]

    const int bid = blockIdx.x;
    const int dir = bid >> 6;
    const int k0 = (bid & 63) * 4;
    const int tid = threadIdx.x;

    // ---- load this block's 16 W_hh rows into smem, once ----
    const float* __restrict__ Wsrc = (dir == 0) ? Whf : Whb;
    for (int f = tid; f < (16 * HH / 4); f += 256) {
        const int r = f >> 6;                   // local row = gate*4+kl
        const int c = (f & 63) * 4;
        const int gate = r >> 2, kl = r & 3;
        *(float4*)&W_s[r * HH + c] =
            *(const float4*)(Wsrc + (size_t)(gate * HH + k0 + kl) * HH + c);
    }

    // update-role mapping (fixed per thread; c lives in a register)
    const int ub  = tid >> 2;        // batch 0..63
    const int ukl = tid & 3;         // channel-in-slice 0..3
    float c_reg = 0.f;

    // dot-role mapping
    const int gate = tid >> 6;       // 0..3
    const int db   = tid & 63;       // batch 0..63

    for (int s = 0; s < TT; s++) {
        const int t = (dir == 0) ? s : (TT - 1 - s);

        if (s > 0) {
            const int tprev = (dir == 0) ? (t - 1) : (t + 1);
            const float* __restrict__ hprev =
                g_h + ((size_t)dir * TT + tprev) * BB * HH;
            __syncthreads();
            // stage h[64][256] into smem (coalesced LDG, conflict-free STS)
            for (int f = tid; f < (BB * HH / 4); f += 256) {
                const int b = f >> 6;
                const int c = (f & 63) * 4;
                *(float4*)&h_s[b * HSTR + c] = *(const float4*)(hprev + b * HH + c);
            }
            __syncthreads();

            // dot: thread (gate, b) -> 4 channels. W loads are warp-uniform
            // broadcasts; h loads conflict-free LDS.128.
            float a0 = 0.f, a1 = 0.f, a2 = 0.f, a3 = 0.f;
            const float4* __restrict__ hv = (const float4*)(h_s + db * HSTR);
            const float4* __restrict__ w0 = (const float4*)(W_s + (gate * 4 + 0) * HH);
            const float4* __restrict__ w1 = (const float4*)(W_s + (gate * 4 + 1) * HH);
            const float4* __restrict__ w2 = (const float4*)(W_s + (gate * 4 + 2) * HH);
            const float4* __restrict__ w3 = (const float4*)(W_s + (gate * 4 + 3) * HH);
#pragma unroll 8
            for (int j = 0; j < HH / 4; j++) {
                const float4 h4 = hv[j];
                const float4 x0 = w0[j];
                a0 += x0.x * h4.x + x0.y * h4.y + x0.z * h4.z + x0.w * h4.w;
                const float4 x1 = w1[j];
                a1 += x1.x * h4.x + x1.y * h4.y + x1.z * h4.z + x1.w * h4.w;
                const float4 x2 = w2[j];
                a2 += x2.x * h4.x + x2.y * h4.y + x2.z * h4.z + x2.w * h4.w;
                const float4 x3 = w3[j];
                a3 += x3.x * h4.x + x3.y * h4.y + x3.z * h4.z + x3.w * h4.w;
            }
            g_s[(gate * 4 + 0) * 65 + db] = a0;
            g_s[(gate * 4 + 1) * 65 + db] = a1;
            g_s[(gate * 4 + 2) * 65 + db] = a2;
            g_s[(gate * 4 + 3) * 65 + db] = a3;
        } else {
            __syncthreads();
            for (int f = tid; f < 16 * 65; f += 256) g_s[f] = 0.f;
        }
        __syncthreads();

        // ---- gate nonlinearities + state update (c in register) ----
        {
            const int kg = k0 + ukl;
            const size_t xbase = (((size_t)dir * TT + t) * BB + ub) * GG + kg;
            const float gi = g_s[(0  + ukl) * 65 + ub] + g_xproj[xbase];
            const float gf = g_s[(4  + ukl) * 65 + ub] + g_xproj[xbase + 256];
            const float gg = g_s[(8  + ukl) * 65 + ub] + g_xproj[xbase + 512];
            const float go = g_s[(12 + ukl) * 65 + ub] + g_xproj[xbase + 768];

            const float ii = 1.f / (1.f + __expf(-gi));
            const float ff = 1.f / (1.f + __expf(-gf));
            const float gt = tanhf(gg);
            const float oo = 1.f / (1.f + __expf(-go));

            c_reg = ff * c_reg + ii * gt;
            const float h = oo * tanhf(c_reg);
            g_h[(((size_t)dir * TT + t) * BB + ub) * HH + kg] = h;
        }

        // ---- grid barrier (release h[t] to all blocks) ----
        if (s < TT - 1) {
            __threadfence();          // release: make this thread's h write GPU-visible
            __syncthreads();
            if (tid == 0) {
                atomicAdd(&g_arrive[s], 1u);
                const volatile unsigned* p = &g_arrive[s];
                while (*p < (unsigned)NBLK) { }
                __threadfence();      // acquire: see peers' h writes
            }
            __syncthreads();
        }
    }
}

// =============================================================================
// Kernel 3: feats[t][b][k] = hcat[t][b][:512] . W_out[k][:512] + b_out[k]
// =============================================================================
__global__ void k_feats(const float* __restrict__ Wout, const float* __restrict__ bout)
{
    __shared__ float Ws[KK * 512];
    __shared__ float bs[KK];
    const int t = blockIdx.x;
    const int tid = threadIdx.x;
    for (int i = tid; i < KK * 512; i += 256) Ws[i] = Wout[i];
    if (tid < KK) bs[tid] = bout[tid];
    __syncthreads();

    const int b = tid >> 2;
    const int kq = tid & 3;
    const float* __restrict__ hf = g_h + (((size_t)0 * TT + t) * BB + b) * HH;
    const float* __restrict__ hb = g_h + (((size_t)1 * TT + t) * BB + b) * HH;

    float acc[3] = {0.f, 0.f, 0.f};
    for (int j = 0; j < HH; j += 4) {
        const float4 hv = *(const float4*)(hf + j);
#pragma unroll
        for (int q = 0; q < 3; q++) {
            const int k = kq * 3 + q;
            const float4 wv = *(const float4*)(Ws + k * 512 + j);
            acc[q] += hv.x * wv.x + hv.y * wv.y + hv.z * wv.z + hv.w * wv.w;
        }
    }
    for (int j = 0; j < HH; j += 4) {
        const float4 hv = *(const float4*)(hb + j);
#pragma unroll
        for (int q = 0; q < 3; q++) {
            const int k = kq * 3 + q;
            const float4 wv = *(const float4*)(Ws + k * 512 + 256 + j);
            acc[q] += hv.x * wv.x + hv.y * wv.y + hv.z * wv.z + hv.w * wv.w;
        }
    }
#pragma unroll
    for (int q = 0; q < 3; q++) {
        const int k = kq * 3 + q;
        g_feats[((size_t)t * BB + b) * KK + k] = acc[q] + bs[k];
    }
}

// =============================================================================
// Kernel 4: CRF Viterbi decode + backtrack. One warp per batch element.
// =============================================================================
__global__ void k_crf(const float* __restrict__ trans,
                      const int* __restrict__ slen,
                      float* __restrict__ out)
{
    __shared__ unsigned char bp_s[TT][KK];
    const int b = blockIdx.x;
    const int lane = threadIdx.x;

    float tr[KK];
#pragma unroll
    for (int kp = 0; kp < KK; kp++)
        tr[kp] = (lane < KK) ? trans[lane * KK + kp] : -1e30f;
    const float tstop = (lane < KK) ? trans[STOP_TAG * KK + lane] : -1e30f;

    float dp = (lane == START_TAG) ? 0.f : NEGV;
    if (lane >= KK) dp = -1e30f;
    const int len = slen[b];

    float fnext = (lane < KK) ? g_feats[((size_t)0 * BB + b) * KK + lane] : 0.f;

    for (int t = 0; t < TT; t++) {
        const float fcur = fnext;
        if (t < TT - 1)
            fnext = (lane < KK) ? g_feats[((size_t)(t + 1) * BB + b) * KK + lane] : 0.f;

        float best = -3.4e38f;
        int barg = 0;
#pragma unroll
        for (int kp = 0; kp < KK; kp++) {
            const float dpv = __shfl_sync(0xffffffffu, dp, kp);
            const float sc = dpv + tr[kp];
            if (sc > best) { best = sc; barg = kp; }   // strict > keeps first index
        }
        const bool valid = (t < len);
        dp = valid ? (best + fcur) : dp;
        const int bpv = valid ? barg : lane;
        if (lane < KK) bp_s[t][lane] = (unsigned char)bpv;
    }

    const float tv = (lane < KK) ? (dp + tstop) : -3.4e38f;
    __syncwarp();

    float best = -3.4e38f;
    int barg = 0;
#pragma unroll
    for (int k = 0; k < KK; k++) {
        const float v = __shfl_sync(0xffffffffu, tv, k);
        if (v > best) { best = v; barg = k; }
    }

    if (lane == 0) {
        out[b] = best;
        int tag = barg;
        float* po = out + BB + (size_t)b * TT;
        for (int t = TT - 1; t >= 0; t--) {
            po[t] = (float)tag;
            tag = (int)bp_s[t][tag];
        }
    }
}

// =============================================================================
// host launcher
// =============================================================================
extern "C" void kernel_launch(void* const* d_in, const int* in_sizes, int n_in,
                              void* d_out, int out_size)
{
    (void)in_sizes; (void)n_in; (void)out_size;
    const int*   sentence = (const int*)  d_in[0];
    const int*   slen     = (const int*)  d_in[1];
    const float* emb      = (const float*)d_in[2];
    const float* Wf_ih    = (const float*)d_in[3];
    const float* Wf_hh    = (const float*)d_in[4];
    const float* bf_ih    = (const float*)d_in[5];
    const float* bf_hh    = (const float*)d_in[6];
    const float* Wb_ih    = (const float*)d_in[7];
    const float* Wb_hh    = (const float*)d_in[8];
    const float* bb_ih    = (const float*)d_in[9];
    const float* bb_hh    = (const float*)d_in[10];
    const float* W_out    = (const float*)d_in[11];
    const float* b_out    = (const float*)d_in[12];
    const float* trans    = (const float*)d_in[13];
    float* out = (float*)d_out;

    // reset per-step barrier counters (graph-capturable async memset)
    void* bar_ptr = nullptr;
    cudaGetSymbolAddress(&bar_ptr, g_arrive);
    cudaMemsetAsync(bar_ptr, 0, TT * sizeof(unsigned));

    const size_t lstm_smem = (size_t)LSTM_SMEM_FLOATS * sizeof(float);
    cudaFuncSetAttribute(k_lstm, cudaFuncAttributeMaxDynamicSharedMemorySize,
                         (int)lstm_smem);

    // 1) input projection for both directions
    k_xproj<<<dim3((BB * TT) / 64, (2 * GG) / 64), 256>>>(
        sentence, emb, Wf_ih, Wb_ih, bf_ih, bf_hh, bb_ih, bb_hh);

    // 2) persistent bidirectional LSTM over all 512 steps
    k_lstm<<<NBLK, 256, lstm_smem>>>(Wf_hh, Wb_hh);

    // 3) emission features
    k_feats<<<TT, 256>>>(W_out, b_out);

    // 4) CRF Viterbi decode
    k_crf<<<BB, 32>>>(trans, slen, out);
}

// round 8
// speedup vs baseline: 1.4783x; 1.0030x over previous
#include <cuda_runtime.h>
#include <cuda_bf16.h>
#include <cstdint>

#define BB 64
#define TT 512
#define EE 256
#define HH 256          // per-direction hidden
#define GG 1024         // 4*H
#define KK 12
#define START_TAG 10
#define STOP_TAG 11
#define NEGV -10000.0f

// ---------------- device scratch (allowed: __device__ globals) ----------------
__device__ float g_xproj[(size_t)2 * TT * BB * GG];   // [dir][t][b][1024]  268 MB
__device__ float g_h[(size_t)2 * TT * BB * HH];       // [dir][t][b][256]   67 MB
__device__ float g_feats[(size_t)TT * BB * KK];       // [t][b][12]
__device__ unsigned g_arrive[TT];                     // per-step barrier counters

// =============================================================================
// Kernel 1: embedding gather + input projection GEMM
//   C[m][n] = emb[tok[m]][:] . W[n][:]  + bias(n),  m in [0,32768), n in [0,2048)
// =============================================================================
__global__ void k_xproj(const int* __restrict__ sent,
                        const float* __restrict__ emb,
                        const float* __restrict__ Wf,
                        const float* __restrict__ Wb,
                        const float* __restrict__ bf_ih, const float* __restrict__ bf_hh,
                        const float* __restrict__ bb_ih, const float* __restrict__ bb_hh)
{
    const int BM = 64, BN = 64, BK = 16;
    __shared__ float As[BK][BM + 4];   // transposed: As[k][m]
    __shared__ float Bs[BK][BN + 4];   // transposed: Bs[k][n]
    __shared__ int   toks[BM];

    const int m0 = blockIdx.x * BM;
    const int n0 = blockIdx.y * BN;
    const int tid = threadIdx.x;
    const int tx = tid & 15;       // 0..15  (n direction)
    const int ty = tid >> 4;       // 0..15  (m direction)

    if (tid < BM) toks[tid] = sent[m0 + tid];
    __syncthreads();

    const int dir = (n0 < GG) ? 0 : 1;
    const int nw0 = (dir == 0) ? n0 : (n0 - GG);
    const float* __restrict__ Wsrc = (dir == 0) ? Wf : Wb;

    float acc[4][4];
#pragma unroll
    for (int i = 0; i < 4; i++)
#pragma unroll
        for (int j = 0; j < 4; j++) acc[i][j] = 0.f;

    const int lr  = tid >> 2;        // 0..63 row for loads
    const int lc4 = (tid & 3) * 4;   // 0,4,8,12 k-offset for loads

    for (int k0 = 0; k0 < EE; k0 += BK) {
        {
            const float4 v = *(const float4*)(emb + (size_t)toks[lr] * EE + k0 + lc4);
            As[lc4 + 0][lr] = v.x; As[lc4 + 1][lr] = v.y;
            As[lc4 + 2][lr] = v.z; As[lc4 + 3][lr] = v.w;
        }
        {
            const float4 v = *(const float4*)(Wsrc + (size_t)(nw0 + lr) * EE + k0 + lc4);
            Bs[lc4 + 0][lr] = v.x; Bs[lc4 + 1][lr] = v.y;
            Bs[lc4 + 2][lr] = v.z; Bs[lc4 + 3][lr] = v.w;
        }
        __syncthreads();
#pragma unroll
        for (int k = 0; k < BK; k++) {
            const float4 a = *(const float4*)&As[k][ty * 4];
            const float4 b = *(const float4*)&Bs[k][tx * 4];
            acc[0][0] += a.x * b.x; acc[0][1] += a.x * b.y; acc[0][2] += a.x * b.z; acc[0][3] += a.x * b.w;
            acc[1][0] += a.y * b.x; acc[1][1] += a.y * b.y; acc[1][2] += a.y * b.z; acc[1][3] += a.y * b.w;
            acc[2][0] += a.z * b.x; acc[2][1] += a.z * b.y; acc[2][2] += a.z * b.z; acc[2][3] += a.z * b.w;
            acc[3][0] += a.w * b.x; acc[3][1] += a.w * b.y; acc[3][2] += a.w * b.z; acc[3][3] += a.w * b.w;
        }
        __syncthreads();
    }

    const int gbase = nw0 + tx * 4;
    float bsum[4];
#pragma unroll
    for (int j = 0; j < 4; j++) {
        const int g = gbase + j;
        bsum[j] = (dir == 0) ? (bf_ih[g] + bf_hh[g]) : (bb_ih[g] + bb_hh[g]);
    }

#pragma unroll
    for (int i = 0; i < 4; i++) {
        const int m = m0 + ty * 4 + i;
        const int t = m & (TT - 1);
        const int b = m >> 9;                       // m / 512
        float4 o;
        o.x = acc[i][0] + bsum[0];
        o.y = acc[i][1] + bsum[1];
        o.z = acc[i][2] + bsum[2];
        o.w = acc[i][3] + bsum[3];
        *(float4*)&g_xproj[(((size_t)dir * TT + t) * BB + b) * GG + gbase] = o;
    }
}

// =============================================================================
// Kernel 2: PERSISTENT bidirectional LSTM.
//   128 blocks (= 2 dirs x 64 channel-slices), all co-resident (<=148 SMs).
//   Each block: caches its 16 W_hh rows in smem ONCE, keeps cell state c in
//   registers, loops over all 512 timesteps with a software grid barrier
//   (per-step arrival counter) between steps.
// =============================================================================
#define HSTR 260   // padded h row stride (floats) — conflict-free LDS.128
#define LSTM_SMEM_FLOATS (BB * HSTR + 16 * HH + 16 * 65)
#define NBLK 128

__global__ void __launch_bounds__(256, 1) k_lstm(const float* __restrict__ Whf,
                                                 const float* __restrict__ Whb)
{
    extern __shared__ float sm[];
    float* h_s = sm;                          // [64][260]
    float* W_s = sm + BB * HSTR;              // [16][256]
    float* g_s = W_s + 16 * HH;               // [16][65]

    const int bid = blockIdx.x;
    const int dir = bid >> 6;
    const int k0 = (bid & 63) * 4;
    const int tid = threadIdx.x;

    // ---- load this block's 16 W_hh rows into smem, once ----
    const float* __restrict__ Wsrc = (dir == 0) ? Whf : Whb;
    for (int f = tid; f < (16 * HH / 4); f += 256) {
        const int r = f >> 6;                   // local row = gate*4+kl
        const int c = (f & 63) * 4;
        const int gate = r >> 2, kl = r & 3;
        *(float4*)&W_s[r * HH + c] =
            *(const float4*)(Wsrc + (size_t)(gate * HH + k0 + kl) * HH + c);
    }

    // update-role mapping (fixed per thread; c lives in a register)
    const int ub  = tid >> 2;        // batch 0..63
    const int ukl = tid & 3;         // channel-in-slice 0..3
    float c_reg = 0.f;

    // dot-role mapping
    const int gate = tid >> 6;       // 0..3
    const int db   = tid & 63;       // batch 0..63

    for (int s = 0; s < TT; s++) {
        const int t = (dir == 0) ? s : (TT - 1 - s);

        if (s > 0) {
            const int tprev = (dir == 0) ? (t - 1) : (t + 1);
            const float* __restrict__ hprev =
                g_h + ((size_t)dir * TT + tprev) * BB * HH;
            __syncthreads();
            // stage h[64][256] into smem (coalesced LDG, conflict-free STS)
            for (int f = tid; f < (BB * HH / 4); f += 256) {
                const int b = f >> 6;
                const int c = (f & 63) * 4;
                *(float4*)&h_s[b * HSTR + c] = *(const float4*)(hprev + b * HH + c);
            }
            __syncthreads();

            // dot: thread (gate, b) -> 4 channels. W loads are warp-uniform
            // broadcasts; h loads conflict-free LDS.128.
            float a0 = 0.f, a1 = 0.f, a2 = 0.f, a3 = 0.f;
            const float4* __restrict__ hv = (const float4*)(h_s + db * HSTR);
            const float4* __restrict__ w0 = (const float4*)(W_s + (gate * 4 + 0) * HH);
            const float4* __restrict__ w1 = (const float4*)(W_s + (gate * 4 + 1) * HH);
            const float4* __restrict__ w2 = (const float4*)(W_s + (gate * 4 + 2) * HH);
            const float4* __restrict__ w3 = (const float4*)(W_s + (gate * 4 + 3) * HH);
#pragma unroll 8
            for (int j = 0; j < HH / 4; j++) {
                const float4 h4 = hv[j];
                const float4 x0 = w0[j];
                a0 += x0.x * h4.x + x0.y * h4.y + x0.z * h4.z + x0.w * h4.w;
                const float4 x1 = w1[j];
                a1 += x1.x * h4.x + x1.y * h4.y + x1.z * h4.z + x1.w * h4.w;
                const float4 x2 = w2[j];
                a2 += x2.x * h4.x + x2.y * h4.y + x2.z * h4.z + x2.w * h4.w;
                const float4 x3 = w3[j];
                a3 += x3.x * h4.x + x3.y * h4.y + x3.z * h4.z + x3.w * h4.w;
            }
            g_s[(gate * 4 + 0) * 65 + db] = a0;
            g_s[(gate * 4 + 1) * 65 + db] = a1;
            g_s[(gate * 4 + 2) * 65 + db] = a2;
            g_s[(gate * 4 + 3) * 65 + db] = a3;
        } else {
            __syncthreads();
            for (int f = tid; f < 16 * 65; f += 256) g_s[f] = 0.f;
        }
        __syncthreads();

        // ---- gate nonlinearities + state update (c in register) ----
        {
            const int kg = k0 + ukl;
            const size_t xbase = (((size_t)dir * TT + t) * BB + ub) * GG + kg;
            const float gi = g_s[(0  + ukl) * 65 + ub] + g_xproj[xbase];
            const float gf = g_s[(4  + ukl) * 65 + ub] + g_xproj[xbase + 256];
            const float gg = g_s[(8  + ukl) * 65 + ub] + g_xproj[xbase + 512];
            const float go = g_s[(12 + ukl) * 65 + ub] + g_xproj[xbase + 768];

            const float ii = 1.f / (1.f + __expf(-gi));
            const float ff = 1.f / (1.f + __expf(-gf));
            const float gt = tanhf(gg);
            const float oo = 1.f / (1.f + __expf(-go));

            c_reg = ff * c_reg + ii * gt;
            const float h = oo * tanhf(c_reg);
            g_h[(((size_t)dir * TT + t) * BB + ub) * HH + kg] = h;
        }

        // ---- grid barrier (release h[t] to all blocks) ----
        if (s < TT - 1) {
            __threadfence();          // release: make this thread's h write GPU-visible
            __syncthreads();
            if (tid == 0) {
                atomicAdd(&g_arrive[s], 1u);
                const volatile unsigned* p = &g_arrive[s];
                while (*p < (unsigned)NBLK) { }
                __threadfence();      // acquire: see peers' h writes
            }
            __syncthreads();
        }
    }
}

// =============================================================================
// Kernel 3: feats[t][b][k] = hcat[t][b][:512] . W_out[k][:512] + b_out[k]
// =============================================================================
__global__ void k_feats(const float* __restrict__ Wout, const float* __restrict__ bout)
{
    __shared__ float Ws[KK * 512];
    __shared__ float bs[KK];
    const int t = blockIdx.x;
    const int tid = threadIdx.x;
    for (int i = tid; i < KK * 512; i += 256) Ws[i] = Wout[i];
    if (tid < KK) bs[tid] = bout[tid];
    __syncthreads();

    const int b = tid >> 2;
    const int kq = tid & 3;
    const float* __restrict__ hf = g_h + (((size_t)0 * TT + t) * BB + b) * HH;
    const float* __restrict__ hb = g_h + (((size_t)1 * TT + t) * BB + b) * HH;

    float acc[3] = {0.f, 0.f, 0.f};
    for (int j = 0; j < HH; j += 4) {
        const float4 hv = *(const float4*)(hf + j);
#pragma unroll
        for (int q = 0; q < 3; q++) {
            const int k = kq * 3 + q;
            const float4 wv = *(const float4*)(Ws + k * 512 + j);
            acc[q] += hv.x * wv.x + hv.y * wv.y + hv.z * wv.z + hv.w * wv.w;
        }
    }
    for (int j = 0; j < HH; j += 4) {
        const float4 hv = *(const float4*)(hb + j);
#pragma unroll
        for (int q = 0; q < 3; q++) {
            const int k = kq * 3 + q;
            const float4 wv = *(const float4*)(Ws + k * 512 + 256 + j);
            acc[q] += hv.x * wv.x + hv.y * wv.y + hv.z * wv.z + hv.w * wv.w;
        }
    }
#pragma unroll
    for (int q = 0; q < 3; q++) {
        const int k = kq * 3 + q;
        g_feats[((size_t)t * BB + b) * KK + k] = acc[q] + bs[k];
    }
}

// =============================================================================
// Kernel 4: CRF Viterbi decode + backtrack. One warp per batch element.
// =============================================================================
__global__ void k_crf(const float* __restrict__ trans,
                      const int* __restrict__ slen,
                      float* __restrict__ out)
{
    __shared__ unsigned char bp_s[TT][KK];
    const int b = blockIdx.x;
    const int lane = threadIdx.x;

    float tr[KK];
#pragma unroll
    for (int kp = 0; kp < KK; kp++)
        tr[kp] = (lane < KK) ? trans[lane * KK + kp] : -1e30f;
    const float tstop = (lane < KK) ? trans[STOP_TAG * KK + lane] : -1e30f;

    float dp = (lane == START_TAG) ? 0.f : NEGV;
    if (lane >= KK) dp = -1e30f;
    const int len = slen[b];

    float fnext = (lane < KK) ? g_feats[((size_t)0 * BB + b) * KK + lane] : 0.f;

    for (int t = 0; t < TT; t++) {
        const float fcur = fnext;
        if (t < TT - 1)
            fnext = (lane < KK) ? g_feats[((size_t)(t + 1) * BB + b) * KK + lane] : 0.f;

        float best = -3.4e38f;
        int barg = 0;
#pragma unroll
        for (int kp = 0; kp < KK; kp++) {
            const float dpv = __shfl_sync(0xffffffffu, dp, kp);
            const float sc = dpv + tr[kp];
            if (sc > best) { best = sc; barg = kp; }   // strict > keeps first index
        }
        const bool valid = (t < len);
        dp = valid ? (best + fcur) : dp;
        const int bpv = valid ? barg : lane;
        if (lane < KK) bp_s[t][lane] = (unsigned char)bpv;
    }

    const float tv = (lane < KK) ? (dp + tstop) : -3.4e38f;
    __syncwarp();

    float best = -3.4e38f;
    int barg = 0;
#pragma unroll
    for (int k = 0; k < KK; k++) {
        const float v = __shfl_sync(0xffffffffu, tv, k);
        if (v > best) { best = v; barg = k; }
    }

    if (lane == 0) {
        out[b] = best;
        int tag = barg;
        float* po = out + BB + (size_t)b * TT;
        for (int t = TT - 1; t >= 0; t--) {
            po[t] = (float)tag;
            tag = (int)bp_s[t][tag];
        }
    }
}

// =============================================================================
// host launcher
// =============================================================================
extern "C" void kernel_launch(void* const* d_in, const int* in_sizes, int n_in,
                              void* d_out, int out_size)
{
    (void)in_sizes; (void)n_in; (void)out_size;
    const int*   sentence = (const int*)  d_in[0];
    const int*   slen     = (const int*)  d_in[1];
    const float* emb      = (const float*)d_in[2];
    const float* Wf_ih    = (const float*)d_in[3];
    const float* Wf_hh    = (const float*)d_in[4];
    const float* bf_ih    = (const float*)d_in[5];
    const float* bf_hh    = (const float*)d_in[6];
    const float* Wb_ih    = (const float*)d_in[7];
    const float* Wb_hh    = (const float*)d_in[8];
    const float* bb_ih    = (const float*)d_in[9];
    const float* bb_hh    = (const float*)d_in[10];
    const float* W_out    = (const float*)d_in[11];
    const float* b_out    = (const float*)d_in[12];
    const float* trans    = (const float*)d_in[13];
    float* out = (float*)d_out;

    // reset per-step barrier counters (graph-capturable async memset)
    void* bar_ptr = nullptr;
    cudaGetSymbolAddress(&bar_ptr, g_arrive);
    cudaMemsetAsync(bar_ptr, 0, TT * sizeof(unsigned));

    const size_t lstm_smem = (size_t)LSTM_SMEM_FLOATS * sizeof(float);
    cudaFuncSetAttribute(k_lstm, cudaFuncAttributeMaxDynamicSharedMemorySize,
                         (int)lstm_smem);

    // 1) input projection for both directions
    k_xproj<<<dim3((BB * TT) / 64, (2 * GG) / 64), 256>>>(
        sentence, emb, Wf_ih, Wb_ih, bf_ih, bf_hh, bb_ih, bb_hh);

    // 2) persistent bidirectional LSTM over all 512 steps
    k_lstm<<<NBLK, 256, lstm_smem>>>(Wf_hh, Wb_hh);

    // 3) emission features
    k_feats<<<TT, 256>>>(W_out, b_out);

    // 4) CRF Viterbi decode
    k_crf<<<BB, 32>>>(trans, slen, out);
}

// round 9
// speedup vs baseline: 1.4866x; 1.0056x over previous
#include <cuda_runtime.h>
#include <cuda_bf16.h>
#include <cstdint>

#define BB 64
#define TT 512
#define EE 256
#define HH 256          // per-direction hidden
#define GG 1024         // 4*H
#define KK 12
#define START_TAG 10
#define STOP_TAG 11
#define NEGV -10000.0f

// ---------------- device scratch (allowed: __device__ globals) ----------------
__device__ float g_xproj[(size_t)2 * TT * BB * GG];   // [dir][t][b][1024]  268 MB
__device__ float g_h[(size_t)2 * TT * BB * HH];       // [dir][t][b][256]   67 MB
__device__ float g_feats[(size_t)TT * BB * KK];       // [t][b][12]
__device__ unsigned g_arrive[TT];                     // per-step barrier counters

// =============================================================================
// Kernel 1: embedding gather + input projection GEMM
//   C[m][n] = emb[tok[m]][:] . W[n][:]  + bias(n),  m in [0,32768), n in [0,2048)
// =============================================================================
__global__ void k_xproj(const int* __restrict__ sent,
                        const float* __restrict__ emb,
                        const float* __restrict__ Wf,
                        const float* __restrict__ Wb,
                        const float* __restrict__ bf_ih, const float* __restrict__ bf_hh,
                        const float* __restrict__ bb_ih, const float* __restrict__ bb_hh)
{
    const int BM = 64, BN = 64, BK = 16;
    __shared__ float As[BK][BM + 4];   // transposed: As[k][m]
    __shared__ float Bs[BK][BN + 4];   // transposed: Bs[k][n]
    __shared__ int   toks[BM];

    const int m0 = blockIdx.x * BM;
    const int n0 = blockIdx.y * BN;
    const int tid = threadIdx.x;
    const int tx = tid & 15;       // 0..15  (n direction)
    const int ty = tid >> 4;       // 0..15  (m direction)

    if (tid < BM) toks[tid] = sent[m0 + tid];
    __syncthreads();

    const int dir = (n0 < GG) ? 0 : 1;
    const int nw0 = (dir == 0) ? n0 : (n0 - GG);
    const float* __restrict__ Wsrc = (dir == 0) ? Wf : Wb;

    float acc[4][4];
#pragma unroll
    for (int i = 0; i < 4; i++)
#pragma unroll
        for (int j = 0; j < 4; j++) acc[i][j] = 0.f;

    const int lr  = tid >> 2;        // 0..63 row for loads
    const int lc4 = (tid & 3) * 4;   // 0,4,8,12 k-offset for loads

    for (int k0 = 0; k0 < EE; k0 += BK) {
        {
            const float4 v = *(const float4*)(emb + (size_t)toks[lr] * EE + k0 + lc4);
            As[lc4 + 0][lr] = v.x; As[lc4 + 1][lr] = v.y;
            As[lc4 + 2][lr] = v.z; As[lc4 + 3][lr] = v.w;
        }
        {
            const float4 v = *(const float4*)(Wsrc + (size_t)(nw0 + lr) * EE + k0 + lc4);
            Bs[lc4 + 0][lr] = v.x; Bs[lc4 + 1][lr] = v.y;
            Bs[lc4 + 2][lr] = v.z; Bs[lc4 + 3][lr] = v.w;
        }
        __syncthreads();
#pragma unroll
        for (int k = 0; k < BK; k++) {
            const float4 a = *(const float4*)&As[k][ty * 4];
            const float4 b = *(const float4*)&Bs[k][tx * 4];
            acc[0][0] += a.x * b.x; acc[0][1] += a.x * b.y; acc[0][2] += a.x * b.z; acc[0][3] += a.x * b.w;
            acc[1][0] += a.y * b.x; acc[1][1] += a.y * b.y; acc[1][2] += a.y * b.z; acc[1][3] += a.y * b.w;
            acc[2][0] += a.z * b.x; acc[2][1] += a.z * b.y; acc[2][2] += a.z * b.z; acc[2][3] += a.z * b.w;
            acc[3][0] += a.w * b.x; acc[3][1] += a.w * b.y; acc[3][2] += a.w * b.z; acc[3][3] += a.w * b.w;
        }
        __syncthreads();
    }

    const int gbase = nw0 + tx * 4;
    float bsum[4];
#pragma unroll
    for (int j = 0; j < 4; j++) {
        const int g = gbase + j;
        bsum[j] = (dir == 0) ? (bf_ih[g] + bf_hh[g]) : (bb_ih[g] + bb_hh[g]);
    }

#pragma unroll
    for (int i = 0; i < 4; i++) {
        const int m = m0 + ty * 4 + i;
        const int t = m & (TT - 1);
        const int b = m >> 9;                       // m / 512
        float4 o;
        o.x = acc[i][0] + bsum[0];
        o.y = acc[i][1] + bsum[1];
        o.z = acc[i][2] + bsum[2];
        o.w = acc[i][3] + bsum[3];
        *(float4*)&g_xproj[(((size_t)dir * TT + t) * BB + b) * GG + gbase] = o;
    }
}

// =============================================================================
// Kernel 2: PERSISTENT bidirectional LSTM.
//   128 blocks (= 2 dirs x 64 channel-slices), all co-resident (<=148 SMs).
//   Each block: caches its 16 W_hh rows in smem ONCE, keeps cell state c in
//   registers, loops over all 512 timesteps with a software grid barrier
//   (per-step arrival counter) between steps.
// =============================================================================
#define HSTR 260   // padded h row stride (floats) — conflict-free LDS.128
#define LSTM_SMEM_FLOATS (BB * HSTR + 16 * HH + 16 * 65)
#define NBLK 128

__global__ void __launch_bounds__(256, 1) k_lstm(const float* __restrict__ Whf,
                                                 const float* __restrict__ Whb)
{
    extern __shared__ float sm[];
    float* h_s = sm;                          // [64][260]
    float* W_s = sm + BB * HSTR;              // [16][256]
    float* g_s = W_s + 16 * HH;               // [16][65]

    const int bid = blockIdx.x;
    const int dir = bid >> 6;
    const int k0 = (bid & 63) * 4;
    const int tid = threadIdx.x;

    // ---- load this block's 16 W_hh rows into smem, once ----
    const float* __restrict__ Wsrc = (dir == 0) ? Whf : Whb;
    for (int f = tid; f < (16 * HH / 4); f += 256) {
        const int r = f >> 6;                   // local row = gate*4+kl
        const int c = (f & 63) * 4;
        const int gate = r >> 2, kl = r & 3;
        *(float4*)&W_s[r * HH + c] =
            *(const float4*)(Wsrc + (size_t)(gate * HH + k0 + kl) * HH + c);
    }

    // update-role mapping (fixed per thread; c lives in a register)
    const int ub  = tid >> 2;        // batch 0..63
    const int ukl = tid & 3;         // channel-in-slice 0..3
    float c_reg = 0.f;

    // dot-role mapping
    const int gate = tid >> 6;       // 0..3
    const int db   = tid & 63;       // batch 0..63

    for (int s = 0; s < TT; s++) {
        const int t = (dir == 0) ? s : (TT - 1 - s);

        if (s > 0) {
            const int tprev = (dir == 0) ? (t - 1) : (t + 1);
            const float* __restrict__ hprev =
                g_h + ((size_t)dir * TT + tprev) * BB * HH;
            __syncthreads();
            // stage h[64][256] into smem (coalesced LDG, conflict-free STS)
            for (int f = tid; f < (BB * HH / 4); f += 256) {
                const int b = f >> 6;
                const int c = (f & 63) * 4;
                *(float4*)&h_s[b * HSTR + c] = *(const float4*)(hprev + b * HH + c);
            }
            __syncthreads();

            // dot: thread (gate, b) -> 4 channels. W loads are warp-uniform
            // broadcasts; h loads conflict-free LDS.128.
            float a0 = 0.f, a1 = 0.f, a2 = 0.f, a3 = 0.f;
            const float4* __restrict__ hv = (const float4*)(h_s + db * HSTR);
            const float4* __restrict__ w0 = (const float4*)(W_s + (gate * 4 + 0) * HH);
            const float4* __restrict__ w1 = (const float4*)(W_s + (gate * 4 + 1) * HH);
            const float4* __restrict__ w2 = (const float4*)(W_s + (gate * 4 + 2) * HH);
            const float4* __restrict__ w3 = (const float4*)(W_s + (gate * 4 + 3) * HH);
#pragma unroll 8
            for (int j = 0; j < HH / 4; j++) {
                const float4 h4 = hv[j];
                const float4 x0 = w0[j];
                a0 += x0.x * h4.x + x0.y * h4.y + x0.z * h4.z + x0.w * h4.w;
                const float4 x1 = w1[j];
                a1 += x1.x * h4.x + x1.y * h4.y + x1.z * h4.z + x1.w * h4.w;
                const float4 x2 = w2[j];
                a2 += x2.x * h4.x + x2.y * h4.y + x2.z * h4.z + x2.w * h4.w;
                const float4 x3 = w3[j];
                a3 += x3.x * h4.x + x3.y * h4.y + x3.z * h4.z + x3.w * h4.w;
            }
            g_s[(gate * 4 + 0) * 65 + db] = a0;
            g_s[(gate * 4 + 1) * 65 + db] = a1;
            g_s[(gate * 4 + 2) * 65 + db] = a2;
            g_s[(gate * 4 + 3) * 65 + db] = a3;
        } else {
            __syncthreads();
            for (int f = tid; f < 16 * 65; f += 256) g_s[f] = 0.f;
        }
        __syncthreads();

        // ---- gate nonlinearities + state update (c in register) ----
        {
            const int kg = k0 + ukl;
            const size_t xbase = (((size_t)dir * TT + t) * BB + ub) * GG + kg;
            const float gi = g_s[(0  + ukl) * 65 + ub] + g_xproj[xbase];
            const float gf = g_s[(4  + ukl) * 65 + ub] + g_xproj[xbase + 256];
            const float gg = g_s[(8  + ukl) * 65 + ub] + g_xproj[xbase + 512];
            const float go = g_s[(12 + ukl) * 65 + ub] + g_xproj[xbase + 768];

            const float ii = 1.f / (1.f + __expf(-gi));
            const float ff = 1.f / (1.f + __expf(-gf));
            const float gt = tanhf(gg);
            const float oo = 1.f / (1.f + __expf(-go));

            c_reg = ff * c_reg + ii * gt;
            const float h = oo * tanhf(c_reg);
            g_h[(((size_t)dir * TT + t) * BB + ub) * HH + kg] = h;
        }

        // ---- grid barrier (release h[t] to all blocks) ----
        if (s < TT - 1) {
            __threadfence();          // release: make this thread's h write GPU-visible
            __syncthreads();
            if (tid == 0) {
                atomicAdd(&g_arrive[s], 1u);
                const volatile unsigned* p = &g_arrive[s];
                while (*p < (unsigned)NBLK) { }
                __threadfence();      // acquire: see peers' h writes
            }
            __syncthreads();
        }
    }
}

// =============================================================================
// Kernel 3: feats[t][b][k] = hcat[t][b][:512] . W_out[k][:512] + b_out[k]
// =============================================================================
__global__ void k_feats(const float* __restrict__ Wout, const float* __restrict__ bout)
{
    __shared__ float Ws[KK * 512];
    __shared__ float bs[KK];
    const int t = blockIdx.x;
    const int tid = threadIdx.x;
    for (int i = tid; i < KK * 512; i += 256) Ws[i] = Wout[i];
    if (tid < KK) bs[tid] = bout[tid];
    __syncthreads();

    const int b = tid >> 2;
    const int kq = tid & 3;
    const float* __restrict__ hf = g_h + (((size_t)0 * TT + t) * BB + b) * HH;
    const float* __restrict__ hb = g_h + (((size_t)1 * TT + t) * BB + b) * HH;

    float acc[3] = {0.f, 0.f, 0.f};
    for (int j = 0; j < HH; j += 4) {
        const float4 hv = *(const float4*)(hf + j);
#pragma unroll
        for (int q = 0; q < 3; q++) {
            const int k = kq * 3 + q;
            const float4 wv = *(const float4*)(Ws + k * 512 + j);
            acc[q] += hv.x * wv.x + hv.y * wv.y + hv.z * wv.z + hv.w * wv.w;
        }
    }
    for (int j = 0; j < HH; j += 4) {
        const float4 hv = *(const float4*)(hb + j);
#pragma unroll
        for (int q = 0; q < 3; q++) {
            const int k = kq * 3 + q;
            const float4 wv = *(const float4*)(Ws + k * 512 + 256 + j);
            acc[q] += hv.x * wv.x + hv.y * wv.y + hv.z * wv.z + hv.w * wv.w;
        }
    }
#pragma unroll
    for (int q = 0; q < 3; q++) {
        const int k = kq * 3 + q;
        g_feats[((size_t)t * BB + b) * KK + k] = acc[q] + bs[k];
    }
}

// =============================================================================
// Kernel 4: CRF Viterbi decode + backtrack. One warp per batch element.
// =============================================================================
__global__ void k_crf(const float* __restrict__ trans,
                      const int* __restrict__ slen,
                      float* __restrict__ out)
{
    __shared__ unsigned char bp_s[TT][KK];
    const int b = blockIdx.x;
    const int lane = threadIdx.x;

    float tr[KK];
#pragma unroll
    for (int kp = 0; kp < KK; kp++)
        tr[kp] = (lane < KK) ? trans[lane * KK + kp] : -1e30f;
    const float tstop = (lane < KK) ? trans[STOP_TAG * KK + lane] : -1e30f;

    float dp = (lane == START_TAG) ? 0.f : NEGV;
    if (lane >= KK) dp = -1e30f;
    const int len = slen[b];

    float fnext = (lane < KK) ? g_feats[((size_t)0 * BB + b) * KK + lane] : 0.f;

    for (int t = 0; t < TT; t++) {
        const float fcur = fnext;
        if (t < TT - 1)
            fnext = (lane < KK) ? g_feats[((size_t)(t + 1) * BB + b) * KK + lane] : 0.f;

        float best = -3.4e38f;
        int barg = 0;
#pragma unroll
        for (int kp = 0; kp < KK; kp++) {
            const float dpv = __shfl_sync(0xffffffffu, dp, kp);
            const float sc = dpv + tr[kp];
            if (sc > best) { best = sc; barg = kp; }   // strict > keeps first index
        }
        const bool valid = (t < len);
        dp = valid ? (best + fcur) : dp;
        const int bpv = valid ? barg : lane;
        if (lane < KK) bp_s[t][lane] = (unsigned char)bpv;
    }

    const float tv = (lane < KK) ? (dp + tstop) : -3.4e38f;
    __syncwarp();

    float best = -3.4e38f;
    int barg = 0;
#pragma unroll
    for (int k = 0; k < KK; k++) {
        const float v = __shfl_sync(0xffffffffu, tv, k);
        if (v > best) { best = v; barg = k; }
    }

    if (lane == 0) {
        out[b] = best;
        int tag = barg;
        float* po = out + BB + (size_t)b * TT;
        for (int t = TT - 1; t >= 0; t--) {
            po[t] = (float)tag;
            tag = (int)bp_s[t][tag];
        }
    }
}

// =============================================================================
// host launcher
// =============================================================================
extern "C" void kernel_launch(void* const* d_in, const int* in_sizes, int n_in,
                              void* d_out, int out_size)
{
    (void)in_sizes; (void)n_in; (void)out_size;
    const int*   sentence = (const int*)  d_in[0];
    const int*   slen     = (const int*)  d_in[1];
    const float* emb      = (const float*)d_in[2];
    const float* Wf_ih    = (const float*)d_in[3];
    const float* Wf_hh    = (const float*)d_in[4];
    const float* bf_ih    = (const float*)d_in[5];
    const float* bf_hh    = (const float*)d_in[6];
    const float* Wb_ih    = (const float*)d_in[7];
    const float* Wb_hh    = (const float*)d_in[8];
    const float* bb_ih    = (const float*)d_in[9];
    const float* bb_hh    = (const float*)d_in[10];
    const float* W_out    = (const float*)d_in[11];
    const float* b_out    = (const float*)d_in[12];
    const float* trans    = (const float*)d_in[13];
    float* out = (float*)d_out;

    // reset per-step barrier counters (graph-capturable async memset)
    void* bar_ptr = nullptr;
    cudaGetSymbolAddress(&bar_ptr, g_arrive);
    cudaMemsetAsync(bar_ptr, 0, TT * sizeof(unsigned));

    const size_t lstm_smem = (size_t)LSTM_SMEM_FLOATS * sizeof(float);
    cudaFuncSetAttribute(k_lstm, cudaFuncAttributeMaxDynamicSharedMemorySize,
                         (int)lstm_smem);

    // 1) input projection for both directions
    k_xproj<<<dim3((BB * TT) / 64, (2 * GG) / 64), 256>>>(
        sentence, emb, Wf_ih, Wb_ih, bf_ih, bf_hh, bb_ih, bb_hh);

    // 2) persistent bidirectional LSTM over all 512 steps
    k_lstm<<<NBLK, 256, lstm_smem>>>(Wf_hh, Wb_hh);

    // 3) emission features
    k_feats<<<TT, 256>>>(W_out, b_out);

    // 4) CRF Viterbi decode
    k_crf<<<BB, 32>>>(trans, slen, out);
}

// round 10
// speedup vs baseline: 1.8335x; 1.2333x over previous
#include <cuda_runtime.h>
#include <cuda_bf16.h>
#include <cstdint>

#define BB 64
#define TT 512
#define EE 256
#define HH 256          // per-direction hidden
#define GG 1024         // 4*H
#define KK 12
#define START_TAG 10
#define STOP_TAG 11
#define NEGV -10000.0f

// ---------------- device scratch (allowed: __device__ globals) ----------------
__device__ float g_xproj[(size_t)2 * TT * BB * GG];   // [dir][t][b][1024]  268 MB
__device__ float g_h[(size_t)2 * TT * BB * HH];       // [dir][t][b][256]   67 MB
__device__ float g_feats[(size_t)TT * BB * KK];       // [t][b][12]
__device__ unsigned g_arrive[4][TT];                  // per-(dir,bg) barrier counters

// =============================================================================
// Kernel 1: embedding gather + input projection GEMM, 128x64 tiles.
//   C[m][n] = emb[tok[m]][:] . W[n][:] + bias(n), m in [0,32768), n in [0,2048)
// =============================================================================
__global__ void k_xproj(const int* __restrict__ sent,
                        const float* __restrict__ emb,
                        const float* __restrict__ Wf,
                        const float* __restrict__ Wb,
                        const float* __restrict__ bf_ih, const float* __restrict__ bf_hh,
                        const float* __restrict__ bb_ih, const float* __restrict__ bb_hh)
{
    const int BM = 128, BN = 64, BK = 16;
    __shared__ float As[BK][BM + 4];   // transposed: As[k][m]
    __shared__ float Bs[BK][BN + 4];   // transposed: Bs[k][n]
    __shared__ int   toks[BM];

    const int m0 = blockIdx.x * BM;
    const int n0 = blockIdx.y * BN;
    const int tid = threadIdx.x;
    const int tx = tid & 15;       // 0..15  (n: 4 cols)
    const int ty = tid >> 4;       // 0..15  (m: 8 rows)

    if (tid < BM) toks[tid] = sent[m0 + tid];
    __syncthreads();

    const int dir = (n0 < GG) ? 0 : 1;
    const int nw0 = (dir == 0) ? n0 : (n0 - GG);
    const float* __restrict__ Wsrc = (dir == 0) ? Wf : Wb;

    float acc[8][4];
#pragma unroll
    for (int i = 0; i < 8; i++)
#pragma unroll
        for (int j = 0; j < 4; j++) acc[i][j] = 0.f;

    for (int k0 = 0; k0 < EE; k0 += BK) {
        // A tile: 128 rows x 16 k = 512 float4; 2 per thread
#pragma unroll
        for (int i = 0; i < 2; i++) {
            const int idx = tid + 256 * i;
            const int r = idx >> 2;
            const int kq = (idx & 3) * 4;
            const float4 v = *(const float4*)(emb + (size_t)toks[r] * EE + k0 + kq);
            As[kq + 0][r] = v.x; As[kq + 1][r] = v.y;
            As[kq + 2][r] = v.z; As[kq + 3][r] = v.w;
        }
        // B tile: 64 rows x 16 k = 256 float4; 1 per thread
        {
            const int r = tid >> 2;
            const int kq = (tid & 3) * 4;
            const float4 v = *(const float4*)(Wsrc + (size_t)(nw0 + r) * EE + k0 + kq);
            Bs[kq + 0][r] = v.x; Bs[kq + 1][r] = v.y;
            Bs[kq + 2][r] = v.z; Bs[kq + 3][r] = v.w;
        }
        __syncthreads();
#pragma unroll
        for (int k = 0; k < BK; k++) {
            const float4 b4 = *(const float4*)&Bs[k][tx * 4];
            const float4 a0 = *(const float4*)&As[k][ty * 8];
            const float4 a1 = *(const float4*)&As[k][ty * 8 + 4];
            acc[0][0] += a0.x * b4.x; acc[0][1] += a0.x * b4.y; acc[0][2] += a0.x * b4.z; acc[0][3] += a0.x * b4.w;
            acc[1][0] += a0.y * b4.x; acc[1][1] += a0.y * b4.y; acc[1][2] += a0.y * b4.z; acc[1][3] += a0.y * b4.w;
            acc[2][0] += a0.z * b4.x; acc[2][1] += a0.z * b4.y; acc[2][2] += a0.z * b4.z; acc[2][3] += a0.z * b4.w;
            acc[3][0] += a0.w * b4.x; acc[3][1] += a0.w * b4.y; acc[3][2] += a0.w * b4.z; acc[3][3] += a0.w * b4.w;
            acc[4][0] += a1.x * b4.x; acc[4][1] += a1.x * b4.y; acc[4][2] += a1.x * b4.z; acc[4][3] += a1.x * b4.w;
            acc[5][0] += a1.y * b4.x; acc[5][1] += a1.y * b4.y; acc[5][2] += a1.y * b4.z; acc[5][3] += a1.y * b4.w;
            acc[6][0] += a1.z * b4.x; acc[6][1] += a1.z * b4.y; acc[6][2] += a1.z * b4.z; acc[6][3] += a1.z * b4.w;
            acc[7][0] += a1.w * b4.x; acc[7][1] += a1.w * b4.y; acc[7][2] += a1.w * b4.z; acc[7][3] += a1.w * b4.w;
        }
        __syncthreads();
    }

    const int gbase = nw0 + tx * 4;
    float bsum[4];
#pragma unroll
    for (int j = 0; j < 4; j++) {
        const int g = gbase + j;
        bsum[j] = (dir == 0) ? (bf_ih[g] + bf_hh[g]) : (bb_ih[g] + bb_hh[g]);
    }

#pragma unroll
    for (int i = 0; i < 8; i++) {
        const int m = m0 + ty * 8 + i;
        const int t = m & (TT - 1);
        const int b = m >> 9;                       // m / 512
        float4 o;
        o.x = acc[i][0] + bsum[0];
        o.y = acc[i][1] + bsum[1];
        o.z = acc[i][2] + bsum[2];
        o.w = acc[i][3] + bsum[3];
        *(float4*)&g_xproj[(((size_t)dir * TT + t) * BB + b) * GG + gbase] = o;
    }
}

// =============================================================================
// Kernel 2: PERSISTENT bidirectional LSTM.
//   grid 128 = dir(2) x rowgroup(32) x batchgroup(2); all co-resident.
//   Block owns 32 gate rows (8 channels x 4 gates) x 32 batches.
//   W_hh slice cached in smem once; cell state in a register; 4 independent
//   32-block software barriers (one per (dir,bg)); xproj gate loads prefetched
//   before the h exchange.
// =============================================================================
#define HSTR 260   // padded h row stride (floats) — conflict-free LDS.128
#define R_BLK 32
#define B_BLK 32
#define LSTM_SMEM_FLOATS (B_BLK * HSTR + R_BLK * HH + R_BLK * 33)
#define NBLK 128
#define NBAR 32

__global__ void __launch_bounds__(256, 1) k_lstm(const float* __restrict__ Whf,
                                                 const float* __restrict__ Whb)
{
    extern __shared__ float sm[];
    float* h_s = sm;                          // [32][260]
    float* W_s = sm + B_BLK * HSTR;           // [32][256]
    float* g_s = W_s + R_BLK * HH;            // [32][33]

    const int bid = blockIdx.x;
    const int dir = bid >> 6;
    const int rg  = (bid >> 1) & 31;
    const int bg  = bid & 1;
    const int k0  = rg * 8;
    const int tid = threadIdx.x;
    const int grp = dir * 2 + bg;

    // ---- cache this block's 32 W_hh rows (gate-major: lr = gate*8 + c) ----
    const float* __restrict__ Wsrc = (dir == 0) ? Whf : Whb;
    for (int f = tid; f < (R_BLK * HH / 4); f += 256) {
        const int lr = f >> 6;
        const int c4 = (f & 63) * 4;
        const int gate = lr >> 3, cc = lr & 7;
        *(float4*)&W_s[lr * HH + c4] =
            *(const float4*)(Wsrc + (size_t)(gate * HH + k0 + cc) * HH + c4);
    }

    // dot-phase roles: rows {rp, rp+16}, batches {bp, bp+16}
    const int rp = tid >> 4;       // 0..15
    const int bp = tid & 15;       // 0..15
    // update roles: channel fast for sector-coalesced xproj/h access
    const int uc = tid & 7;        // 0..7  channel within slice
    const int ub = tid >> 3;       // 0..31 batch within group
    const int gb = bg * B_BLK + ub;

    float c_reg = 0.f;
    __syncthreads();

    for (int s = 0; s < TT; s++) {
        const int t = (dir == 0) ? s : (TT - 1 - s);

        // prefetch xproj gate pre-activations (independent of h exchange)
        const size_t xbase = (((size_t)dir * TT + t) * BB + gb) * GG + k0 + uc;
        const float xi = g_xproj[xbase];
        const float xf = g_xproj[xbase + 256];
        const float xg = g_xproj[xbase + 512];
        const float xo = g_xproj[xbase + 768];

        if (s > 0) {
            const int tprev = (dir == 0) ? (t - 1) : (t + 1);
            const float* __restrict__ hprev =
                g_h + (((size_t)dir * TT + tprev) * BB + bg * B_BLK) * HH;
            // stage h[32][256]
            for (int f = tid; f < (B_BLK * HH / 4); f += 256) {
                const int b = f >> 6;
                const int c4 = (f & 63) * 4;
                *(float4*)&h_s[b * HSTR + c4] = *(const float4*)(hprev + b * HH + c4);
            }
            __syncthreads();

            float a00 = 0.f, a01 = 0.f, a10 = 0.f, a11 = 0.f;
            const float4* __restrict__ w0 = (const float4*)(W_s + rp * HH);
            const float4* __restrict__ w1 = (const float4*)(W_s + (rp + 16) * HH);
            const float4* __restrict__ h0 = (const float4*)(h_s + bp * HSTR);
            const float4* __restrict__ h1 = (const float4*)(h_s + (bp + 16) * HSTR);
#pragma unroll 8
            for (int j = 0; j < HH / 4; j++) {
                const float4 x0 = w0[j];
                const float4 x1 = w1[j];
                const float4 ha = h0[j];
                const float4 hb = h1[j];
                a00 += x0.x * ha.x + x0.y * ha.y + x0.z * ha.z + x0.w * ha.w;
                a01 += x0.x * hb.x + x0.y * hb.y + x0.z * hb.z + x0.w * hb.w;
                a10 += x1.x * ha.x + x1.y * ha.y + x1.z * ha.z + x1.w * ha.w;
                a11 += x1.x * hb.x + x1.y * hb.y + x1.z * hb.z + x1.w * hb.w;
            }
            g_s[rp * 33 + bp]             = a00;
            g_s[rp * 33 + bp + 16]        = a01;
            g_s[(rp + 16) * 33 + bp]      = a10;
            g_s[(rp + 16) * 33 + bp + 16] = a11;
        } else {
            for (int f = tid; f < R_BLK * 33; f += 256) g_s[f] = 0.f;
        }
        __syncthreads();

        // ---- gate nonlinearities + state update (c in register) ----
        {
            const float gi = g_s[(0 * 8 + uc) * 33 + ub] + xi;
            const float gf = g_s[(1 * 8 + uc) * 33 + ub] + xf;
            const float gg = g_s[(2 * 8 + uc) * 33 + ub] + xg;
            const float go = g_s[(3 * 8 + uc) * 33 + ub] + xo;

            const float ii = 1.f / (1.f + __expf(-gi));
            const float ff = 1.f / (1.f + __expf(-gf));
            const float gt = tanhf(gg);
            const float oo = 1.f / (1.f + __expf(-go));

            c_reg = ff * c_reg + ii * gt;
            const float h = oo * tanhf(c_reg);
            g_h[(((size_t)dir * TT + t) * BB + gb) * HH + k0 + uc] = h;
        }

        // ---- 32-block software barrier within (dir, bg) group ----
        if (s < TT - 1) {
            __threadfence();          // release h[t]
            __syncthreads();
            if (tid == 0) {
                atomicAdd(&g_arrive[grp][s], 1u);
                const volatile unsigned* p = &g_arrive[grp][s];
                while (*p < (unsigned)NBAR) { }
                __threadfence();      // acquire peers' h writes
            }
            __syncthreads();
        }
    }
}

// =============================================================================
// Kernel 3: feats[t][b][k] = hcat[t][b][:512] . W_out[k][:512] + b_out[k]
// =============================================================================
__global__ void k_feats(const float* __restrict__ Wout, const float* __restrict__ bout)
{
    __shared__ float Ws[KK * 512];
    __shared__ float bs[KK];
    const int t = blockIdx.x;
    const int tid = threadIdx.x;
    for (int i = tid; i < KK * 512; i += 256) Ws[i] = Wout[i];
    if (tid < KK) bs[tid] = bout[tid];
    __syncthreads();

    const int b = tid >> 2;
    const int kq = tid & 3;
    const float* __restrict__ hf = g_h + (((size_t)0 * TT + t) * BB + b) * HH;
    const float* __restrict__ hb = g_h + (((size_t)1 * TT + t) * BB + b) * HH;

    float acc[3] = {0.f, 0.f, 0.f};
    for (int j = 0; j < HH; j += 4) {
        const float4 hv = *(const float4*)(hf + j);
#pragma unroll
        for (int q = 0; q < 3; q++) {
            const int k = kq * 3 + q;
            const float4 wv = *(const float4*)(Ws + k * 512 + j);
            acc[q] += hv.x * wv.x + hv.y * wv.y + hv.z * wv.z + hv.w * wv.w;
        }
    }
    for (int j = 0; j < HH; j += 4) {
        const float4 hv = *(const float4*)(hb + j);
#pragma unroll
        for (int q = 0; q < 3; q++) {
            const int k = kq * 3 + q;
            const float4 wv = *(const float4*)(Ws + k * 512 + 256 + j);
            acc[q] += hv.x * wv.x + hv.y * wv.y + hv.z * wv.z + hv.w * wv.w;
        }
    }
#pragma unroll
    for (int q = 0; q < 3; q++) {
        const int k = kq * 3 + q;
        g_feats[((size_t)t * BB + b) * KK + k] = acc[q] + bs[k];
    }
}

// =============================================================================
// Kernel 4: CRF Viterbi decode + backtrack. One warp per batch element.
//   Argmax via tree-max + equality mask + ffs (first-index tie-break, matching
//   jnp.argmax) — removes the 12-deep predicated compare chain.
// =============================================================================
__global__ void k_crf(const float* __restrict__ trans,
                      const int* __restrict__ slen,
                      float* __restrict__ out)
{
    __shared__ unsigned char bp_s[TT][KK];
    const int b = blockIdx.x;
    const int lane = threadIdx.x;

    float tr[KK];
#pragma unroll
    for (int kp = 0; kp < KK; kp++)
        tr[kp] = (lane < KK) ? trans[lane * KK + kp] : -1e30f;
    const float tstop = (lane < KK) ? trans[STOP_TAG * KK + lane] : -1e30f;

    float dp = (lane == START_TAG) ? 0.f : NEGV;
    if (lane >= KK) dp = -1e30f;
    const int len = slen[b];

    float fnext = (lane < KK) ? g_feats[((size_t)0 * BB + b) * KK + lane] : 0.f;

    for (int t = 0; t < TT; t++) {
        const float fcur = fnext;
        if (t < TT - 1)
            fnext = (lane < KK) ? g_feats[((size_t)(t + 1) * BB + b) * KK + lane] : 0.f;

        // independent scores
        float sc[KK];
#pragma unroll
        for (int kp = 0; kp < KK; kp++)
            sc[kp] = __shfl_sync(0xffffffffu, dp, kp) + tr[kp];

        // tree max (depth 4)
        float m0 = fmaxf(sc[0], sc[1]);
        float m1 = fmaxf(sc[2], sc[3]);
        float m2 = fmaxf(sc[4], sc[5]);
        float m3 = fmaxf(sc[6], sc[7]);
        float m4 = fmaxf(sc[8], sc[9]);
        float m5 = fmaxf(sc[10], sc[11]);
        m0 = fmaxf(m0, m1); m2 = fmaxf(m2, m3); m4 = fmaxf(m4, m5);
        const float best = fmaxf(fmaxf(m0, m2), m4);

        // first-index argmax via equality mask
        unsigned mask = 0;
#pragma unroll
        for (int kp = 0; kp < KK; kp++)
            mask |= (sc[kp] == best) ? (1u << kp) : 0u;
        const int barg = __ffs(mask) - 1;

        const bool valid = (t < len);
        dp = valid ? (best + fcur) : dp;
        const int bpv = valid ? barg : lane;
        if (lane < KK) bp_s[t][lane] = (unsigned char)bpv;
    }

    // terminal: max over lanes with first-index tie-break
    const float tv = (lane < KK) ? (dp + tstop) : -3.4e38f;
    float wmax = tv;
#pragma unroll
    for (int off = 16; off > 0; off >>= 1)
        wmax = fmaxf(wmax, __shfl_xor_sync(0xffffffffu, wmax, off));
    const unsigned winners = __ballot_sync(0xffffffffu, tv == wmax);
    const int barg = __ffs(winners) - 1;

    if (lane == 0) {
        out[b] = wmax;
        int tag = barg;
        float* po = out + BB + (size_t)b * TT;
        for (int t = TT - 1; t >= 0; t--) {
            po[t] = (float)tag;
            tag = (int)bp_s[t][tag];
        }
    }
}

// =============================================================================
// host launcher
// =============================================================================
extern "C" void kernel_launch(void* const* d_in, const int* in_sizes, int n_in,
                              void* d_out, int out_size)
{
    (void)in_sizes; (void)n_in; (void)out_size;
    const int*   sentence = (const int*)  d_in[0];
    const int*   slen     = (const int*)  d_in[1];
    const float* emb      = (const float*)d_in[2];
    const float* Wf_ih    = (const float*)d_in[3];
    const float* Wf_hh    = (const float*)d_in[4];
    const float* bf_ih    = (const float*)d_in[5];
    const float* bf_hh    = (const float*)d_in[6];
    const float* Wb_ih    = (const float*)d_in[7];
    const float* Wb_hh    = (const float*)d_in[8];
    const float* bb_ih    = (const float*)d_in[9];
    const float* bb_hh    = (const float*)d_in[10];
    const float* W_out    = (const float*)d_in[11];
    const float* b_out    = (const float*)d_in[12];
    const float* trans    = (const float*)d_in[13];
    float* out = (float*)d_out;

    // reset barrier counters (graph-capturable async memset)
    void* bar_ptr = nullptr;
    cudaGetSymbolAddress(&bar_ptr, g_arrive);
    cudaMemsetAsync(bar_ptr, 0, 4 * TT * sizeof(unsigned));

    const size_t lstm_smem = (size_t)LSTM_SMEM_FLOATS * sizeof(float);
    cudaFuncSetAttribute(k_lstm, cudaFuncAttributeMaxDynamicSharedMemorySize,
                         (int)lstm_smem);

    // 1) input projection for both directions (128x64 tiles)
    k_xproj<<<dim3((BB * TT) / 128, (2 * GG) / 64), 256>>>(
        sentence, emb, Wf_ih, Wb_ih, bf_ih, bf_hh, bb_ih, bb_hh);

    // 2) persistent bidirectional LSTM over all 512 steps
    k_lstm<<<NBLK, 256, lstm_smem>>>(Wf_hh, Wb_hh);

    // 3) emission features
    k_feats<<<TT, 256>>>(W_out, b_out);

    // 4) CRF Viterbi decode
    k_crf<<<BB, 32>>>(trans, slen, out);
}

// round 11
// speedup vs baseline: 1.8422x; 1.0047x over previous
#include <cuda_runtime.h>
#include <cuda_bf16.h>
#include <cstdint>

#define BB 64
#define TT 512
#define EE 256
#define HH 256          // per-direction hidden
#define GG 1024         // 4*H
#define KK 12
#define START_TAG 10
#define STOP_TAG 11
#define NEGV -10000.0f

// ---------------- device scratch (allowed: __device__ globals) ----------------
__device__ float g_xproj[(size_t)2 * TT * BB * GG];   // [dir][t][b][1024]  268 MB
__device__ float g_h[(size_t)2 * TT * BB * HH];       // [dir][t][b][256]   67 MB
__device__ float g_feats[(size_t)TT * BB * KK];       // [t][b][12]
__device__ unsigned g_arrive[4][TT];                  // per-(dir,bg) barrier counters

// =============================================================================
// Kernel 1: embedding gather + input projection GEMM, 128x64 tiles.
//   C[m][n] = emb[tok[m]][:] . W[n][:] + bias(n), m in [0,32768), n in [0,2048)
// =============================================================================
__global__ void k_xproj(const int* __restrict__ sent,
                        const float* __restrict__ emb,
                        const float* __restrict__ Wf,
                        const float* __restrict__ Wb,
                        const float* __restrict__ bf_ih, const float* __restrict__ bf_hh,
                        const float* __restrict__ bb_ih, const float* __restrict__ bb_hh)
{
    const int BM = 128, BN = 64, BK = 16;
    __shared__ float As[BK][BM + 4];   // transposed: As[k][m]
    __shared__ float Bs[BK][BN + 4];   // transposed: Bs[k][n]
    __shared__ int   toks[BM];

    const int m0 = blockIdx.x * BM;
    const int n0 = blockIdx.y * BN;
    const int tid = threadIdx.x;
    const int tx = tid & 15;       // 0..15  (n: 4 cols)
    const int ty = tid >> 4;       // 0..15  (m: 8 rows)

    if (tid < BM) toks[tid] = sent[m0 + tid];
    __syncthreads();

    const int dir = (n0 < GG) ? 0 : 1;
    const int nw0 = (dir == 0) ? n0 : (n0 - GG);
    const float* __restrict__ Wsrc = (dir == 0) ? Wf : Wb;

    float acc[8][4];
#pragma unroll
    for (int i = 0; i < 8; i++)
#pragma unroll
        for (int j = 0; j < 4; j++) acc[i][j] = 0.f;

    for (int k0 = 0; k0 < EE; k0 += BK) {
        // A tile: 128 rows x 16 k = 512 float4; 2 per thread
#pragma unroll
        for (int i = 0; i < 2; i++) {
            const int idx = tid + 256 * i;
            const int r = idx >> 2;
            const int kq = (idx & 3) * 4;
            const float4 v = *(const float4*)(emb + (size_t)toks[r] * EE + k0 + kq);
            As[kq + 0][r] = v.x; As[kq + 1][r] = v.y;
            As[kq + 2][r] = v.z; As[kq + 3][r] = v.w;
        }
        // B tile: 64 rows x 16 k = 256 float4; 1 per thread
        {
            const int r = tid >> 2;
            const int kq = (tid & 3) * 4;
            const float4 v = *(const float4*)(Wsrc + (size_t)(nw0 + r) * EE + k0 + kq);
            Bs[kq + 0][r] = v.x; Bs[kq + 1][r] = v.y;
            Bs[kq + 2][r] = v.z; Bs[kq + 3][r] = v.w;
        }
        __syncthreads();
#pragma unroll
        for (int k = 0; k < BK; k++) {
            const float4 b4 = *(const float4*)&Bs[k][tx * 4];
            const float4 a0 = *(const float4*)&As[k][ty * 8];
            const float4 a1 = *(const float4*)&As[k][ty * 8 + 4];
            acc[0][0] += a0.x * b4.x; acc[0][1] += a0.x * b4.y; acc[0][2] += a0.x * b4.z; acc[0][3] += a0.x * b4.w;
            acc[1][0] += a0.y * b4.x; acc[1][1] += a0.y * b4.y; acc[1][2] += a0.y * b4.z; acc[1][3] += a0.y * b4.w;
            acc[2][0] += a0.z * b4.x; acc[2][1] += a0.z * b4.y; acc[2][2] += a0.z * b4.z; acc[2][3] += a0.z * b4.w;
            acc[3][0] += a0.w * b4.x; acc[3][1] += a0.w * b4.y; acc[3][2] += a0.w * b4.z; acc[3][3] += a0.w * b4.w;
            acc[4][0] += a1.x * b4.x; acc[4][1] += a1.x * b4.y; acc[4][2] += a1.x * b4.z; acc[4][3] += a1.x * b4.w;
            acc[5][0] += a1.y * b4.x; acc[5][1] += a1.y * b4.y; acc[5][2] += a1.y * b4.z; acc[5][3] += a1.y * b4.w;
            acc[6][0] += a1.z * b4.x; acc[6][1] += a1.z * b4.y; acc[6][2] += a1.z * b4.z; acc[6][3] += a1.z * b4.w;
            acc[7][0] += a1.w * b4.x; acc[7][1] += a1.w * b4.y; acc[7][2] += a1.w * b4.z; acc[7][3] += a1.w * b4.w;
        }
        __syncthreads();
    }

    const int gbase = nw0 + tx * 4;
    float bsum[4];
#pragma unroll
    for (int j = 0; j < 4; j++) {
        const int g = gbase + j;
        bsum[j] = (dir == 0) ? (bf_ih[g] + bf_hh[g]) : (bb_ih[g] + bb_hh[g]);
    }

#pragma unroll
    for (int i = 0; i < 8; i++) {
        const int m = m0 + ty * 8 + i;
        const int t = m & (TT - 1);
        const int b = m >> 9;                       // m / 512
        float4 o;
        o.x = acc[i][0] + bsum[0];
        o.y = acc[i][1] + bsum[1];
        o.z = acc[i][2] + bsum[2];
        o.w = acc[i][3] + bsum[3];
        *(float4*)&g_xproj[(((size_t)dir * TT + t) * BB + b) * GG + gbase] = o;
    }
}

// =============================================================================
// Kernel 2: PERSISTENT bidirectional LSTM.
//   grid 128 = dir(2) x rowgroup(32) x batchgroup(2); all co-resident.
//   Block owns 32 gate rows (8 channels x 4 gates) x 32 batches.
//   W_hh slice cached in smem once; cell state in a register; 4 independent
//   32-block software barriers (one per (dir,bg)); xproj gate loads prefetched
//   before the h exchange.
// =============================================================================
#define HSTR 260   // padded h row stride (floats) — conflict-free LDS.128
#define R_BLK 32
#define B_BLK 32
#define LSTM_SMEM_FLOATS (B_BLK * HSTR + R_BLK * HH + R_BLK * 33)
#define NBLK 128
#define NBAR 32

__global__ void __launch_bounds__(256, 1) k_lstm(const float* __restrict__ Whf,
                                                 const float* __restrict__ Whb)
{
    extern __shared__ float sm[];
    float* h_s = sm;                          // [32][260]
    float* W_s = sm + B_BLK * HSTR;           // [32][256]
    float* g_s = W_s + R_BLK * HH;            // [32][33]

    const int bid = blockIdx.x;
    const int dir = bid >> 6;
    const int rg  = (bid >> 1) & 31;
    const int bg  = bid & 1;
    const int k0  = rg * 8;
    const int tid = threadIdx.x;
    const int grp = dir * 2 + bg;

    // ---- cache this block's 32 W_hh rows (gate-major: lr = gate*8 + c) ----
    const float* __restrict__ Wsrc = (dir == 0) ? Whf : Whb;
    for (int f = tid; f < (R_BLK * HH / 4); f += 256) {
        const int lr = f >> 6;
        const int c4 = (f & 63) * 4;
        const int gate = lr >> 3, cc = lr & 7;
        *(float4*)&W_s[lr * HH + c4] =
            *(const float4*)(Wsrc + (size_t)(gate * HH + k0 + cc) * HH + c4);
    }

    // dot-phase roles: rows {rp, rp+16}, batches {bp, bp+16}
    const int rp = tid >> 4;       // 0..15
    const int bp = tid & 15;       // 0..15
    // update roles: channel fast for sector-coalesced xproj/h access
    const int uc = tid & 7;        // 0..7  channel within slice
    const int ub = tid >> 3;       // 0..31 batch within group
    const int gb = bg * B_BLK + ub;

    float c_reg = 0.f;
    __syncthreads();

    for (int s = 0; s < TT; s++) {
        const int t = (dir == 0) ? s : (TT - 1 - s);

        // prefetch xproj gate pre-activations (independent of h exchange)
        const size_t xbase = (((size_t)dir * TT + t) * BB + gb) * GG + k0 + uc;
        const float xi = g_xproj[xbase];
        const float xf = g_xproj[xbase + 256];
        const float xg = g_xproj[xbase + 512];
        const float xo = g_xproj[xbase + 768];

        if (s > 0) {
            const int tprev = (dir == 0) ? (t - 1) : (t + 1);
            const float* __restrict__ hprev =
                g_h + (((size_t)dir * TT + tprev) * BB + bg * B_BLK) * HH;
            // stage h[32][256]
            for (int f = tid; f < (B_BLK * HH / 4); f += 256) {
                const int b = f >> 6;
                const int c4 = (f & 63) * 4;
                *(float4*)&h_s[b * HSTR + c4] = *(const float4*)(hprev + b * HH + c4);
            }
            __syncthreads();

            float a00 = 0.f, a01 = 0.f, a10 = 0.f, a11 = 0.f;
            const float4* __restrict__ w0 = (const float4*)(W_s + rp * HH);
            const float4* __restrict__ w1 = (const float4*)(W_s + (rp + 16) * HH);
            const float4* __restrict__ h0 = (const float4*)(h_s + bp * HSTR);
            const float4* __restrict__ h1 = (const float4*)(h_s + (bp + 16) * HSTR);
#pragma unroll 8
            for (int j = 0; j < HH / 4; j++) {
                const float4 x0 = w0[j];
                const float4 x1 = w1[j];
                const float4 ha = h0[j];
                const float4 hb = h1[j];
                a00 += x0.x * ha.x + x0.y * ha.y + x0.z * ha.z + x0.w * ha.w;
                a01 += x0.x * hb.x + x0.y * hb.y + x0.z * hb.z + x0.w * hb.w;
                a10 += x1.x * ha.x + x1.y * ha.y + x1.z * ha.z + x1.w * ha.w;
                a11 += x1.x * hb.x + x1.y * hb.y + x1.z * hb.z + x1.w * hb.w;
            }
            g_s[rp * 33 + bp]             = a00;
            g_s[rp * 33 + bp + 16]        = a01;
            g_s[(rp + 16) * 33 + bp]      = a10;
            g_s[(rp + 16) * 33 + bp + 16] = a11;
        } else {
            for (int f = tid; f < R_BLK * 33; f += 256) g_s[f] = 0.f;
        }
        __syncthreads();

        // ---- gate nonlinearities + state update (c in register) ----
        {
            const float gi = g_s[(0 * 8 + uc) * 33 + ub] + xi;
            const float gf = g_s[(1 * 8 + uc) * 33 + ub] + xf;
            const float gg = g_s[(2 * 8 + uc) * 33 + ub] + xg;
            const float go = g_s[(3 * 8 + uc) * 33 + ub] + xo;

            const float ii = 1.f / (1.f + __expf(-gi));
            const float ff = 1.f / (1.f + __expf(-gf));
            const float gt = tanhf(gg);
            const float oo = 1.f / (1.f + __expf(-go));

            c_reg = ff * c_reg + ii * gt;
            const float h = oo * tanhf(c_reg);
            g_h[(((size_t)dir * TT + t) * BB + gb) * HH + k0 + uc] = h;
        }

        // ---- 32-block software barrier within (dir, bg) group ----
        if (s < TT - 1) {
            __threadfence();          // release h[t]
            __syncthreads();
            if (tid == 0) {
                atomicAdd(&g_arrive[grp][s], 1u);
                const volatile unsigned* p = &g_arrive[grp][s];
                while (*p < (unsigned)NBAR) { }
                __threadfence();      // acquire peers' h writes
            }
            __syncthreads();
        }
    }
}

// =============================================================================
// Kernel 3: feats[t][b][k] = hcat[t][b][:512] . W_out[k][:512] + b_out[k]
// =============================================================================
__global__ void k_feats(const float* __restrict__ Wout, const float* __restrict__ bout)
{
    __shared__ float Ws[KK * 512];
    __shared__ float bs[KK];
    const int t = blockIdx.x;
    const int tid = threadIdx.x;
    for (int i = tid; i < KK * 512; i += 256) Ws[i] = Wout[i];
    if (tid < KK) bs[tid] = bout[tid];
    __syncthreads();

    const int b = tid >> 2;
    const int kq = tid & 3;
    const float* __restrict__ hf = g_h + (((size_t)0 * TT + t) * BB + b) * HH;
    const float* __restrict__ hb = g_h + (((size_t)1 * TT + t) * BB + b) * HH;

    float acc[3] = {0.f, 0.f, 0.f};
    for (int j = 0; j < HH; j += 4) {
        const float4 hv = *(const float4*)(hf + j);
#pragma unroll
        for (int q = 0; q < 3; q++) {
            const int k = kq * 3 + q;
            const float4 wv = *(const float4*)(Ws + k * 512 + j);
            acc[q] += hv.x * wv.x + hv.y * wv.y + hv.z * wv.z + hv.w * wv.w;
        }
    }
    for (int j = 0; j < HH; j += 4) {
        const float4 hv = *(const float4*)(hb + j);
#pragma unroll
        for (int q = 0; q < 3; q++) {
            const int k = kq * 3 + q;
            const float4 wv = *(const float4*)(Ws + k * 512 + 256 + j);
            acc[q] += hv.x * wv.x + hv.y * wv.y + hv.z * wv.z + hv.w * wv.w;
        }
    }
#pragma unroll
    for (int q = 0; q < 3; q++) {
        const int k = kq * 3 + q;
        g_feats[((size_t)t * BB + b) * KK + k] = acc[q] + bs[k];
    }
}

// =============================================================================
// Kernel 4: CRF Viterbi decode + backtrack. One warp per batch element.
//   Argmax via tree-max + equality mask + ffs (first-index tie-break, matching
//   jnp.argmax) — removes the 12-deep predicated compare chain.
// =============================================================================
__global__ void k_crf(const float* __restrict__ trans,
                      const int* __restrict__ slen,
                      float* __restrict__ out)
{
    __shared__ unsigned char bp_s[TT][KK];
    const int b = blockIdx.x;
    const int lane = threadIdx.x;

    float tr[KK];
#pragma unroll
    for (int kp = 0; kp < KK; kp++)
        tr[kp] = (lane < KK) ? trans[lane * KK + kp] : -1e30f;
    const float tstop = (lane < KK) ? trans[STOP_TAG * KK + lane] : -1e30f;

    float dp = (lane == START_TAG) ? 0.f : NEGV;
    if (lane >= KK) dp = -1e30f;
    const int len = slen[b];

    float fnext = (lane < KK) ? g_feats[((size_t)0 * BB + b) * KK + lane] : 0.f;

    for (int t = 0; t < TT; t++) {
        const float fcur = fnext;
        if (t < TT - 1)
            fnext = (lane < KK) ? g_feats[((size_t)(t + 1) * BB + b) * KK + lane] : 0.f;

        // independent scores
        float sc[KK];
#pragma unroll
        for (int kp = 0; kp < KK; kp++)
            sc[kp] = __shfl_sync(0xffffffffu, dp, kp) + tr[kp];

        // tree max (depth 4)
        float m0 = fmaxf(sc[0], sc[1]);
        float m1 = fmaxf(sc[2], sc[3]);
        float m2 = fmaxf(sc[4], sc[5]);
        float m3 = fmaxf(sc[6], sc[7]);
        float m4 = fmaxf(sc[8], sc[9]);
        float m5 = fmaxf(sc[10], sc[11]);
        m0 = fmaxf(m0, m1); m2 = fmaxf(m2, m3); m4 = fmaxf(m4, m5);
        const float best = fmaxf(fmaxf(m0, m2), m4);

        // first-index argmax via equality mask
        unsigned mask = 0;
#pragma unroll
        for (int kp = 0; kp < KK; kp++)
            mask |= (sc[kp] == best) ? (1u << kp) : 0u;
        const int barg = __ffs(mask) - 1;

        const bool valid = (t < len);
        dp = valid ? (best + fcur) : dp;
        const int bpv = valid ? barg : lane;
        if (lane < KK) bp_s[t][lane] = (unsigned char)bpv;
    }

    // terminal: max over lanes with first-index tie-break
    const float tv = (lane < KK) ? (dp + tstop) : -3.4e38f;
    float wmax = tv;
#pragma unroll
    for (int off = 16; off > 0; off >>= 1)
        wmax = fmaxf(wmax, __shfl_xor_sync(0xffffffffu, wmax, off));
    const unsigned winners = __ballot_sync(0xffffffffu, tv == wmax);
    const int barg = __ffs(winners) - 1;

    if (lane == 0) {
        out[b] = wmax;
        int tag = barg;
        float* po = out + BB + (size_t)b * TT;
        for (int t = TT - 1; t >= 0; t--) {
            po[t] = (float)tag;
            tag = (int)bp_s[t][tag];
        }
    }
}

// =============================================================================
// host launcher
// =============================================================================
extern "C" void kernel_launch(void* const* d_in, const int* in_sizes, int n_in,
                              void* d_out, int out_size)
{
    (void)in_sizes; (void)n_in; (void)out_size;
    const int*   sentence = (const int*)  d_in[0];
    const int*   slen     = (const int*)  d_in[1];
    const float* emb      = (const float*)d_in[2];
    const float* Wf_ih    = (const float*)d_in[3];
    const float* Wf_hh    = (const float*)d_in[4];
    const float* bf_ih    = (const float*)d_in[5];
    const float* bf_hh    = (const float*)d_in[6];
    const float* Wb_ih    = (const float*)d_in[7];
    const float* Wb_hh    = (const float*)d_in[8];
    const float* bb_ih    = (const float*)d_in[9];
    const float* bb_hh    = (const float*)d_in[10];
    const float* W_out    = (const float*)d_in[11];
    const float* b_out    = (const float*)d_in[12];
    const float* trans    = (const float*)d_in[13];
    float* out = (float*)d_out;

    // reset barrier counters (graph-capturable async memset)
    void* bar_ptr = nullptr;
    cudaGetSymbolAddress(&bar_ptr, g_arrive);
    cudaMemsetAsync(bar_ptr, 0, 4 * TT * sizeof(unsigned));

    const size_t lstm_smem = (size_t)LSTM_SMEM_FLOATS * sizeof(float);
    cudaFuncSetAttribute(k_lstm, cudaFuncAttributeMaxDynamicSharedMemorySize,
                         (int)lstm_smem);

    // 1) input projection for both directions (128x64 tiles)
    k_xproj<<<dim3((BB * TT) / 128, (2 * GG) / 64), 256>>>(
        sentence, emb, Wf_ih, Wb_ih, bf_ih, bf_hh, bb_ih, bb_hh);

    // 2) persistent bidirectional LSTM over all 512 steps
    k_lstm<<<NBLK, 256, lstm_smem>>>(Wf_hh, Wb_hh);

    // 3) emission features
    k_feats<<<TT, 256>>>(W_out, b_out);

    // 4) CRF Viterbi decode
    k_crf<<<BB, 32>>>(trans, slen, out);
}

// round 12
// speedup vs baseline: 1.8456x; 1.0019x over previous
#include <cuda_runtime.h>
#include <cuda_bf16.h>
#include <cstdint>

#define BB 64
#define TT 512
#define EE 256
#define HH 256          // per-direction hidden
#define GG 1024         // 4*H
#define KK 12
#define START_TAG 10
#define STOP_TAG 11
#define NEGV -10000.0f

// ---------------- device scratch (allowed: __device__ globals) ----------------
__device__ float g_xproj[(size_t)2 * TT * BB * GG];   // [dir][t][b][1024]  268 MB
__device__ float g_h[(size_t)2 * TT * BB * HH];       // [dir][t][b][256]   67 MB
__device__ float g_feats[(size_t)TT * BB * KK];       // [t][b][12]
__device__ unsigned g_arrive[4][TT];                  // per-(dir,bg) barrier counters

// =============================================================================
// Kernel 1: embedding gather + input projection GEMM, 128x64 tiles.
//   C[m][n] = emb[tok[m]][:] . W[n][:] + bias(n), m in [0,32768), n in [0,2048)
// =============================================================================
__global__ void k_xproj(const int* __restrict__ sent,
                        const float* __restrict__ emb,
                        const float* __restrict__ Wf,
                        const float* __restrict__ Wb,
                        const float* __restrict__ bf_ih, const float* __restrict__ bf_hh,
                        const float* __restrict__ bb_ih, const float* __restrict__ bb_hh)
{
    const int BM = 128, BN = 64, BK = 16;
    __shared__ float As[BK][BM + 4];   // transposed: As[k][m]
    __shared__ float Bs[BK][BN + 4];   // transposed: Bs[k][n]
    __shared__ int   toks[BM];

    const int m0 = blockIdx.x * BM;
    const int n0 = blockIdx.y * BN;
    const int tid = threadIdx.x;
    const int tx = tid & 15;       // 0..15  (n: 4 cols)
    const int ty = tid >> 4;       // 0..15  (m: 8 rows)

    if (tid < BM) toks[tid] = sent[m0 + tid];
    __syncthreads();

    const int dir = (n0 < GG) ? 0 : 1;
    const int nw0 = (dir == 0) ? n0 : (n0 - GG);
    const float* __restrict__ Wsrc = (dir == 0) ? Wf : Wb;

    float acc[8][4];
#pragma unroll
    for (int i = 0; i < 8; i++)
#pragma unroll
        for (int j = 0; j < 4; j++) acc[i][j] = 0.f;

    for (int k0 = 0; k0 < EE; k0 += BK) {
        // A tile: 128 rows x 16 k = 512 float4; 2 per thread
#pragma unroll
        for (int i = 0; i < 2; i++) {
            const int idx = tid + 256 * i;
            const int r = idx >> 2;
            const int kq = (idx & 3) * 4;
            const float4 v = *(const float4*)(emb + (size_t)toks[r] * EE + k0 + kq);
            As[kq + 0][r] = v.x; As[kq + 1][r] = v.y;
            As[kq + 2][r] = v.z; As[kq + 3][r] = v.w;
        }
        // B tile: 64 rows x 16 k = 256 float4; 1 per thread
        {
            const int r = tid >> 2;
            const int kq = (tid & 3) * 4;
            const float4 v = *(const float4*)(Wsrc + (size_t)(nw0 + r) * EE + k0 + kq);
            Bs[kq + 0][r] = v.x; Bs[kq + 1][r] = v.y;
            Bs[kq + 2][r] = v.z; Bs[kq + 3][r] = v.w;
        }
        __syncthreads();
#pragma unroll
        for (int k = 0; k < BK; k++) {
            const float4 b4 = *(const float4*)&Bs[k][tx * 4];
            const float4 a0 = *(const float4*)&As[k][ty * 8];
            const float4 a1 = *(const float4*)&As[k][ty * 8 + 4];
            acc[0][0] += a0.x * b4.x; acc[0][1] += a0.x * b4.y; acc[0][2] += a0.x * b4.z; acc[0][3] += a0.x * b4.w;
            acc[1][0] += a0.y * b4.x; acc[1][1] += a0.y * b4.y; acc[1][2] += a0.y * b4.z; acc[1][3] += a0.y * b4.w;
            acc[2][0] += a0.z * b4.x; acc[2][1] += a0.z * b4.y; acc[2][2] += a0.z * b4.z; acc[2][3] += a0.z * b4.w;
            acc[3][0] += a0.w * b4.x; acc[3][1] += a0.w * b4.y; acc[3][2] += a0.w * b4.z; acc[3][3] += a0.w * b4.w;
            acc[4][0] += a1.x * b4.x; acc[4][1] += a1.x * b4.y; acc[4][2] += a1.x * b4.z; acc[4][3] += a1.x * b4.w;
            acc[5][0] += a1.y * b4.x; acc[5][1] += a1.y * b4.y; acc[5][2] += a1.y * b4.z; acc[5][3] += a1.y * b4.w;
            acc[6][0] += a1.z * b4.x; acc[6][1] += a1.z * b4.y; acc[6][2] += a1.z * b4.z; acc[6][3] += a1.z * b4.w;
            acc[7][0] += a1.w * b4.x; acc[7][1] += a1.w * b4.y; acc[7][2] += a1.w * b4.z; acc[7][3] += a1.w * b4.w;
        }
        __syncthreads();
    }

    const int gbase = nw0 + tx * 4;
    float bsum[4];
#pragma unroll
    for (int j = 0; j < 4; j++) {
        const int g = gbase + j;
        bsum[j] = (dir == 0) ? (bf_ih[g] + bf_hh[g]) : (bb_ih[g] + bb_hh[g]);
    }

#pragma unroll
    for (int i = 0; i < 8; i++) {
        const int m = m0 + ty * 8 + i;
        const int t = m & (TT - 1);
        const int b = m >> 9;                       // m / 512
        float4 o;
        o.x = acc[i][0] + bsum[0];
        o.y = acc[i][1] + bsum[1];
        o.z = acc[i][2] + bsum[2];
        o.w = acc[i][3] + bsum[3];
        *(float4*)&g_xproj[(((size_t)dir * TT + t) * BB + b) * GG + gbase] = o;
    }
}

// =============================================================================
// Kernel 2: PERSISTENT bidirectional LSTM.
//   grid 128 = dir(2) x rowgroup(32) x batchgroup(2); all co-resident.
//   Block owns 32 gate rows (8 channels x 4 gates) x 32 batches.
//   W_hh slice cached in smem once; cell state in a register; 4 independent
//   32-block software barriers (one per (dir,bg)); xproj gate loads prefetched
//   before the h exchange.
// =============================================================================
#define HSTR 260   // padded h row stride (floats) — conflict-free LDS.128
#define R_BLK 32
#define B_BLK 32
#define LSTM_SMEM_FLOATS (B_BLK * HSTR + R_BLK * HH + R_BLK * 33)
#define NBLK 128
#define NBAR 32

__global__ void __launch_bounds__(256, 1) k_lstm(const float* __restrict__ Whf,
                                                 const float* __restrict__ Whb)
{
    extern __shared__ float sm[];
    float* h_s = sm;                          // [32][260]
    float* W_s = sm + B_BLK * HSTR;           // [32][256]
    float* g_s = W_s + R_BLK * HH;            // [32][33]

    const int bid = blockIdx.x;
    const int dir = bid >> 6;
    const int rg  = (bid >> 1) & 31;
    const int bg  = bid & 1;
    const int k0  = rg * 8;
    const int tid = threadIdx.x;
    const int grp = dir * 2 + bg;

    // ---- cache this block's 32 W_hh rows (gate-major: lr = gate*8 + c) ----
    const float* __restrict__ Wsrc = (dir == 0) ? Whf : Whb;
    for (int f = tid; f < (R_BLK * HH / 4); f += 256) {
        const int lr = f >> 6;
        const int c4 = (f & 63) * 4;
        const int gate = lr >> 3, cc = lr & 7;
        *(float4*)&W_s[lr * HH + c4] =
            *(const float4*)(Wsrc + (size_t)(gate * HH + k0 + cc) * HH + c4);
    }

    // dot-phase roles: rows {rp, rp+16}, batches {bp, bp+16}
    const int rp = tid >> 4;       // 0..15
    const int bp = tid & 15;       // 0..15
    // update roles: channel fast for sector-coalesced xproj/h access
    const int uc = tid & 7;        // 0..7  channel within slice
    const int ub = tid >> 3;       // 0..31 batch within group
    const int gb = bg * B_BLK + ub;

    float c_reg = 0.f;
    __syncthreads();

    for (int s = 0; s < TT; s++) {
        const int t = (dir == 0) ? s : (TT - 1 - s);

        // prefetch xproj gate pre-activations (independent of h exchange)
        const size_t xbase = (((size_t)dir * TT + t) * BB + gb) * GG + k0 + uc;
        const float xi = g_xproj[xbase];
        const float xf = g_xproj[xbase + 256];
        const float xg = g_xproj[xbase + 512];
        const float xo = g_xproj[xbase + 768];

        if (s > 0) {
            const int tprev = (dir == 0) ? (t - 1) : (t + 1);
            const float* __restrict__ hprev =
                g_h + (((size_t)dir * TT + tprev) * BB + bg * B_BLK) * HH;
            // stage h[32][256]
            for (int f = tid; f < (B_BLK * HH / 4); f += 256) {
                const int b = f >> 6;
                const int c4 = (f & 63) * 4;
                *(float4*)&h_s[b * HSTR + c4] = *(const float4*)(hprev + b * HH + c4);
            }
            __syncthreads();

            float a00 = 0.f, a01 = 0.f, a10 = 0.f, a11 = 0.f;
            const float4* __restrict__ w0 = (const float4*)(W_s + rp * HH);
            const float4* __restrict__ w1 = (const float4*)(W_s + (rp + 16) * HH);
            const float4* __restrict__ h0 = (const float4*)(h_s + bp * HSTR);
            const float4* __restrict__ h1 = (const float4*)(h_s + (bp + 16) * HSTR);
#pragma unroll 8
            for (int j = 0; j < HH / 4; j++) {
                const float4 x0 = w0[j];
                const float4 x1 = w1[j];
                const float4 ha = h0[j];
                const float4 hb = h1[j];
                a00 += x0.x * ha.x + x0.y * ha.y + x0.z * ha.z + x0.w * ha.w;
                a01 += x0.x * hb.x + x0.y * hb.y + x0.z * hb.z + x0.w * hb.w;
                a10 += x1.x * ha.x + x1.y * ha.y + x1.z * ha.z + x1.w * ha.w;
                a11 += x1.x * hb.x + x1.y * hb.y + x1.z * hb.z + x1.w * hb.w;
            }
            g_s[rp * 33 + bp]             = a00;
            g_s[rp * 33 + bp + 16]        = a01;
            g_s[(rp + 16) * 33 + bp]      = a10;
            g_s[(rp + 16) * 33 + bp + 16] = a11;
        } else {
            for (int f = tid; f < R_BLK * 33; f += 256) g_s[f] = 0.f;
        }
        __syncthreads();

        // ---- gate nonlinearities + state update (c in register) ----
        {
            const float gi = g_s[(0 * 8 + uc) * 33 + ub] + xi;
            const float gf = g_s[(1 * 8 + uc) * 33 + ub] + xf;
            const float gg = g_s[(2 * 8 + uc) * 33 + ub] + xg;
            const float go = g_s[(3 * 8 + uc) * 33 + ub] + xo;

            const float ii = 1.f / (1.f + __expf(-gi));
            const float ff = 1.f / (1.f + __expf(-gf));
            const float gt = tanhf(gg);
            const float oo = 1.f / (1.f + __expf(-go));

            c_reg = ff * c_reg + ii * gt;
            const float h = oo * tanhf(c_reg);
            g_h[(((size_t)dir * TT + t) * BB + gb) * HH + k0 + uc] = h;
        }

        // ---- 32-block software barrier within (dir, bg) group ----
        if (s < TT - 1) {
            __threadfence();          // release h[t]
            __syncthreads();
            if (tid == 0) {
                atomicAdd(&g_arrive[grp][s], 1u);
                const volatile unsigned* p = &g_arrive[grp][s];
                while (*p < (unsigned)NBAR) { }
                __threadfence();      // acquire peers' h writes
            }
            __syncthreads();
        }
    }
}

// =============================================================================
// Kernel 3: feats[t][b][k] = hcat[t][b][:512] . W_out[k][:512] + b_out[k]
// =============================================================================
__global__ void k_feats(const float* __restrict__ Wout, const float* __restrict__ bout)
{
    __shared__ float Ws[KK * 512];
    __shared__ float bs[KK];
    const int t = blockIdx.x;
    const int tid = threadIdx.x;
    for (int i = tid; i < KK * 512; i += 256) Ws[i] = Wout[i];
    if (tid < KK) bs[tid] = bout[tid];
    __syncthreads();

    const int b = tid >> 2;
    const int kq = tid & 3;
    const float* __restrict__ hf = g_h + (((size_t)0 * TT + t) * BB + b) * HH;
    const float* __restrict__ hb = g_h + (((size_t)1 * TT + t) * BB + b) * HH;

    float acc[3] = {0.f, 0.f, 0.f};
    for (int j = 0; j < HH; j += 4) {
        const float4 hv = *(const float4*)(hf + j);
#pragma unroll
        for (int q = 0; q < 3; q++) {
            const int k = kq * 3 + q;
            const float4 wv = *(const float4*)(Ws + k * 512 + j);
            acc[q] += hv.x * wv.x + hv.y * wv.y + hv.z * wv.z + hv.w * wv.w;
        }
    }
    for (int j = 0; j < HH; j += 4) {
        const float4 hv = *(const float4*)(hb + j);
#pragma unroll
        for (int q = 0; q < 3; q++) {
            const int k = kq * 3 + q;
            const float4 wv = *(const float4*)(Ws + k * 512 + 256 + j);
            acc[q] += hv.x * wv.x + hv.y * wv.y + hv.z * wv.z + hv.w * wv.w;
        }
    }
#pragma unroll
    for (int q = 0; q < 3; q++) {
        const int k = kq * 3 + q;
        g_feats[((size_t)t * BB + b) * KK + k] = acc[q] + bs[k];
    }
}

// =============================================================================
// Kernel 4: CRF Viterbi decode + backtrack. One warp per batch element.
//   Argmax via tree-max + equality mask + ffs (first-index tie-break, matching
//   jnp.argmax) — removes the 12-deep predicated compare chain.
// =============================================================================
__global__ void k_crf(const float* __restrict__ trans,
                      const int* __restrict__ slen,
                      float* __restrict__ out)
{
    __shared__ unsigned char bp_s[TT][KK];
    const int b = blockIdx.x;
    const int lane = threadIdx.x;

    float tr[KK];
#pragma unroll
    for (int kp = 0; kp < KK; kp++)
        tr[kp] = (lane < KK) ? trans[lane * KK + kp] : -1e30f;
    const float tstop = (lane < KK) ? trans[STOP_TAG * KK + lane] : -1e30f;

    float dp = (lane == START_TAG) ? 0.f : NEGV;
    if (lane >= KK) dp = -1e30f;
    const int len = slen[b];

    float fnext = (lane < KK) ? g_feats[((size_t)0 * BB + b) * KK + lane] : 0.f;

    for (int t = 0; t < TT; t++) {
        const float fcur = fnext;
        if (t < TT - 1)
            fnext = (lane < KK) ? g_feats[((size_t)(t + 1) * BB + b) * KK + lane] : 0.f;

        // independent scores
        float sc[KK];
#pragma unroll
        for (int kp = 0; kp < KK; kp++)
            sc[kp] = __shfl_sync(0xffffffffu, dp, kp) + tr[kp];

        // tree max (depth 4)
        float m0 = fmaxf(sc[0], sc[1]);
        float m1 = fmaxf(sc[2], sc[3]);
        float m2 = fmaxf(sc[4], sc[5]);
        float m3 = fmaxf(sc[6], sc[7]);
        float m4 = fmaxf(sc[8], sc[9]);
        float m5 = fmaxf(sc[10], sc[11]);
        m0 = fmaxf(m0, m1); m2 = fmaxf(m2, m3); m4 = fmaxf(m4, m5);
        const float best = fmaxf(fmaxf(m0, m2), m4);

        // first-index argmax via equality mask
        unsigned mask = 0;
#pragma unroll
        for (int kp = 0; kp < KK; kp++)
            mask |= (sc[kp] == best) ? (1u << kp) : 0u;
        const int barg = __ffs(mask) - 1;

        const bool valid = (t < len);
        dp = valid ? (best + fcur) : dp;
        const int bpv = valid ? barg : lane;
        if (lane < KK) bp_s[t][lane] = (unsigned char)bpv;
    }

    // terminal: max over lanes with first-index tie-break
    const float tv = (lane < KK) ? (dp + tstop) : -3.4e38f;
    float wmax = tv;
#pragma unroll
    for (int off = 16; off > 0; off >>= 1)
        wmax = fmaxf(wmax, __shfl_xor_sync(0xffffffffu, wmax, off));
    const unsigned winners = __ballot_sync(0xffffffffu, tv == wmax);
    const int barg = __ffs(winners) - 1;

    if (lane == 0) {
        out[b] = wmax;
        int tag = barg;
        float* po = out + BB + (size_t)b * TT;
        for (int t = TT - 1; t >= 0; t--) {
            po[t] = (float)tag;
            tag = (int)bp_s[t][tag];
        }
    }
}

// =============================================================================
// host launcher
// =============================================================================
extern "C" void kernel_launch(void* const* d_in, const int* in_sizes, int n_in,
                              void* d_out, int out_size)
{
    (void)in_sizes; (void)n_in; (void)out_size;
    const int*   sentence = (const int*)  d_in[0];
    const int*   slen     = (const int*)  d_in[1];
    const float* emb      = (const float*)d_in[2];
    const float* Wf_ih    = (const float*)d_in[3];
    const float* Wf_hh    = (const float*)d_in[4];
    const float* bf_ih    = (const float*)d_in[5];
    const float* bf_hh    = (const float*)d_in[6];
    const float* Wb_ih    = (const float*)d_in[7];
    const float* Wb_hh    = (const float*)d_in[8];
    const float* bb_ih    = (const float*)d_in[9];
    const float* bb_hh    = (const float*)d_in[10];
    const float* W_out    = (const float*)d_in[11];
    const float* b_out    = (const float*)d_in[12];
    const float* trans    = (const float*)d_in[13];
    float* out = (float*)d_out;

    // reset barrier counters (graph-capturable async memset)
    void* bar_ptr = nullptr;
    cudaGetSymbolAddress(&bar_ptr, g_arrive);
    cudaMemsetAsync(bar_ptr, 0, 4 * TT * sizeof(unsigned));

    const size_t lstm_smem = (size_t)LSTM_SMEM_FLOATS * sizeof(float);
    cudaFuncSetAttribute(k_lstm, cudaFuncAttributeMaxDynamicSharedMemorySize,
                         (int)lstm_smem);

    // 1) input projection for both directions (128x64 tiles)
    k_xproj<<<dim3((BB * TT) / 128, (2 * GG) / 64), 256>>>(
        sentence, emb, Wf_ih, Wb_ih, bf_ih, bf_hh, bb_ih, bb_hh);

    // 2) persistent bidirectional LSTM over all 512 steps
    k_lstm<<<NBLK, 256, lstm_smem>>>(Wf_hh, Wb_hh);

    // 3) emission features
    k_feats<<<TT, 256>>>(W_out, b_out);

    // 4) CRF Viterbi decode
    k_crf<<<BB, 32>>>(trans, slen, out);
}